// round 2
// baseline (speedup 1.0000x reference)
#include <cuda_runtime.h>
#include <math.h>

#define HH      256
#define G4      1024
#define BATCH   256
#define WIN     512
#define TT      519     // W + MAXLAG
#define MAXLAG  7
#define SREP    100
#define NDEC    25600   // BATCH * SREP
#define PSTEPS  24
#define ESTEPS  512
#define ENC_BLOCKS 128  // 8 batch-tiles (32) x 16 unit-tiles (16)

// ---------------- scratch (static device globals; no allocation) ----------------
__device__ __align__(128) float g_scaled[BATCH * TT];
__device__ float g_loc[BATCH];
__device__ float g_scale[BATCH];

__device__ __align__(128) float g_h0e[2][BATCH * HH];
__device__ __align__(128) float g_c0e[BATCH * HH];
__device__ __align__(128) float g_h1e[2][BATCH * HH];
__device__ __align__(128) float g_c1e[BATCH * HH];

__device__ __align__(128) float g_h0d[2][NDEC * HH];
__device__ __align__(128) float g_c0d[NDEC * HH];
__device__ __align__(128) float g_h1d[2][NDEC * HH];
__device__ __align__(128) float g_c1d[NDEC * HH];

// per-row history: [0..6] = last 7 scaled values, [7..30] = decoder samples
__device__ __align__(128) float g_hist[NDEC * 32];

// grid barrier state
__device__ unsigned g_bar_count = 0;
__device__ volatile unsigned g_bar_gen = 0;

__device__ __forceinline__ float sigf(float x) { return 1.0f / (1.0f + expf(-x)); }

// ---------------- normalization ----------------
__global__ void norm_kernel(const float* __restrict__ tp) {
    int b = blockIdx.x;
    int tid = threadIdx.x;
    const float* row = tp + b * TT;

    double s = 0.0, q = 0.0;
    for (int j = tid; j < WIN; j += blockDim.x) {
        double v = (double)row[MAXLAG + j];
        s += v; q += v * v;
    }
    __shared__ double ss[256], sq[256];
    ss[tid] = s; sq[tid] = q;
    __syncthreads();
    for (int o = 128; o > 0; o >>= 1) {
        if (tid < o) { ss[tid] += ss[tid + o]; sq[tid] += sq[tid + o]; }
        __syncthreads();
    }
    __shared__ float smean, sscale;
    if (tid == 0) {
        double mean = ss[0] / (double)WIN;
        double var  = sq[0] / (double)WIN - mean * mean;
        if (var < 0.0) var = 0.0;
        float sd = (float)sqrt(var);
        float sc = (sd < 1e-10f) ? 1.0f : sd;
        smean = (float)mean; sscale = sc;
        g_loc[b] = (float)mean; g_scale[b] = sc;
    }
    __syncthreads();
    float m = smean, sc = sscale;
    for (int j = tid; j < TT; j += blockDim.x)
        g_scaled[b * TT + j] = (row[j] - m) / sc;
}

// ---------------- zero encoder state ----------------
__global__ void zero_enc_kernel() {
    int i = blockIdx.x * blockDim.x + threadIdx.x;
    if (i < BATCH * HH) {
        g_h0e[0][i] = 0.f; g_c0e[i] = 0.f;
        g_h1e[0][i] = 0.f; g_c1e[i] = 0.f;
    }
}

// ---------------- software grid barrier (all blocks must be resident) ----------------
__device__ __forceinline__ void grid_barrier(unsigned nb) {
    __syncthreads();
    if (threadIdx.x == 0) {
        unsigned gen = g_bar_gen;          // read BEFORE arriving
        __threadfence();
        if (atomicAdd(&g_bar_count, 1u) == nb - 1) {
            g_bar_count = 0;
            __threadfence();
            g_bar_gen = gen + 1;
        } else {
            while (g_bar_gen == gen) { }
        }
    }
    __syncthreads();
}

// ---------------- persistent encoder: 512 steps x 2 layers in ONE launch ----------------
// 128 blocks, each owns a fixed 32(batch) x 16(unit) tile of the gate matrix.
// h buffers ping-pong; cross-SM h reads use __ldcg (L1 is not coherent within a launch).
__global__ void __launch_bounds__(256) encoder_kernel(
    const float* __restrict__ w_ih0, const float* __restrict__ w_hh0,
    const float* __restrict__ b_ih0, const float* __restrict__ b_hh0,
    const float* __restrict__ w_ih1, const float* __restrict__ w_hh1,
    const float* __restrict__ b_ih1, const float* __restrict__ b_hh1)
{
    __shared__ float sA[32][17];
    __shared__ float sW[64][17];
    __shared__ float sXA[32][8];
    __shared__ float sXW[64][8];

    const int t  = threadIdx.x;
    const int tg = t & 15;          // unit within tile
    const int tb = t >> 4;          // 0..15 -> batch rows tb, tb+16
    const int b0 = (blockIdx.x & 7) * 32;
    const int u0 = (blockIdx.x >> 3) * 16;

    // hoist: lag weight tile (constant over steps)
    if (t < 64) {
        int grow = u0 + (t & 15) + ((t >> 4) << 8);
#pragma unroll
        for (int k = 0; k < 7; k++) sXW[t][k] = w_ih0[grow * 7 + k];
    }

    // per-thread gate biases
    const int u = u0 + tg;
    const float bI0 = b_ih0[u]       + b_hh0[u];
    const float bF0 = b_ih0[u + 256] + b_hh0[u + 256];
    const float bG0 = b_ih0[u + 512] + b_hh0[u + 512];
    const float bO0 = b_ih0[u + 768] + b_hh0[u + 768];
    const float bI1 = b_ih1[u]       + b_hh1[u];
    const float bF1 = b_ih1[u + 256] + b_hh1[u + 256];
    const float bG1 = b_ih1[u + 512] + b_hh1[u + 512];
    const float bO1 = b_ih1[u + 768] + b_hh1[u + 768];

    const int lr = t >> 2;           // smem load row
    const int lc = (t & 3) * 4;      // k-quad
    const int lgrow = u0 + (lr & 15) + ((lr >> 4) << 8);   // gate row for sW loads

    for (int step = 0; step < ESTEPS; step++) {
        const int pa = step & 1, pb = pa ^ 1;
        const float* h0a = g_h0e[pa];
        float*       h0b = g_h0e[pb];
        const float* h1a = g_h1e[pa];
        float*       h1b = g_h1e[pb];

        // ===== layer 0 =====
        float acc[2][4];
#pragma unroll
        for (int i = 0; i < 2; i++)
#pragma unroll
            for (int j = 0; j < 4; j++) acc[i][j] = 0.f;

        // lag inputs for this step
        if (t < 32) {
            const float* xr = g_scaled + (b0 + t) * TT + step + 6;
#pragma unroll
            for (int k = 0; k < 7; k++) sXA[t][k] = xr[-k];
        }
        __syncthreads();
#pragma unroll
        for (int k = 0; k < 7; k++) {
            float wv[4];
#pragma unroll
            for (int gi = 0; gi < 4; gi++) wv[gi] = sXW[tg + 16 * gi][k];
#pragma unroll
            for (int bi = 0; bi < 2; bi++) {
                float a = sXA[tb + 16 * bi][k];
#pragma unroll
                for (int gi = 0; gi < 4; gi++) acc[bi][gi] = fmaf(a, wv[gi], acc[bi][gi]);
            }
        }

        // h0 @ w_hh0^T
        for (int k0 = 0; k0 < HH; k0 += 16) {
            __syncthreads();
            if (t < 128) {
                float4 av = __ldcg((const float4*)(h0a + (b0 + lr) * HH + k0 + lc));
                sA[lr][lc + 0] = av.x; sA[lr][lc + 1] = av.y; sA[lr][lc + 2] = av.z; sA[lr][lc + 3] = av.w;
            }
            float4 wv = *(const float4*)(w_hh0 + lgrow * HH + k0 + lc);
            sW[lr][lc + 0] = wv.x; sW[lr][lc + 1] = wv.y; sW[lr][lc + 2] = wv.z; sW[lr][lc + 3] = wv.w;
            __syncthreads();
#pragma unroll
            for (int kk = 0; kk < 16; kk++) {
                float w4[4], a2[2];
#pragma unroll
                for (int gi = 0; gi < 4; gi++) w4[gi] = sW[tg + 16 * gi][kk];
#pragma unroll
                for (int bi = 0; bi < 2; bi++) a2[bi] = sA[tb + 16 * bi][kk];
#pragma unroll
                for (int bi = 0; bi < 2; bi++)
#pragma unroll
                    for (int gi = 0; gi < 4; gi++)
                        acc[bi][gi] = fmaf(a2[bi], w4[gi], acc[bi][gi]);
            }
        }

        // epilogue layer 0
#pragma unroll
        for (int bi = 0; bi < 2; bi++) {
            int b = b0 + tb + 16 * bi;
            int idx = b * HH + u;
            float gi_ = acc[bi][0] + bI0;
            float gf  = acc[bi][1] + bF0;
            float gg  = acc[bi][2] + bG0;
            float go  = acc[bi][3] + bO0;
            float c = g_c0e[idx];
            float cn = sigf(gf) * c + sigf(gi_) * tanhf(gg);
            g_c0e[idx] = cn;
            h0b[idx] = sigf(go) * tanhf(cn);
        }
        grid_barrier(ENC_BLOCKS);

        // ===== layer 1 : gates = h0_new @ w_ih1^T + h1 @ w_hh1^T =====
#pragma unroll
        for (int i = 0; i < 2; i++)
#pragma unroll
            for (int j = 0; j < 4; j++) acc[i][j] = 0.f;

        for (int pass = 0; pass < 2; pass++) {
            const float* act = pass ? h1a : h0b;
            const float* wgt = pass ? w_hh1 : w_ih1;
            for (int k0 = 0; k0 < HH; k0 += 16) {
                __syncthreads();
                if (t < 128) {
                    float4 av = __ldcg((const float4*)(act + (b0 + lr) * HH + k0 + lc));
                    sA[lr][lc + 0] = av.x; sA[lr][lc + 1] = av.y; sA[lr][lc + 2] = av.z; sA[lr][lc + 3] = av.w;
                }
                float4 wv = *(const float4*)(wgt + lgrow * HH + k0 + lc);
                sW[lr][lc + 0] = wv.x; sW[lr][lc + 1] = wv.y; sW[lr][lc + 2] = wv.z; sW[lr][lc + 3] = wv.w;
                __syncthreads();
#pragma unroll
                for (int kk = 0; kk < 16; kk++) {
                    float w4[4], a2[2];
#pragma unroll
                    for (int gi = 0; gi < 4; gi++) w4[gi] = sW[tg + 16 * gi][kk];
#pragma unroll
                    for (int bi = 0; bi < 2; bi++) a2[bi] = sA[tb + 16 * bi][kk];
#pragma unroll
                    for (int bi = 0; bi < 2; bi++)
#pragma unroll
                        for (int gi = 0; gi < 4; gi++)
                            acc[bi][gi] = fmaf(a2[bi], w4[gi], acc[bi][gi]);
                }
            }
        }

#pragma unroll
        for (int bi = 0; bi < 2; bi++) {
            int b = b0 + tb + 16 * bi;
            int idx = b * HH + u;
            float gi_ = acc[bi][0] + bI1;
            float gf  = acc[bi][1] + bF1;
            float gg  = acc[bi][2] + bG1;
            float go  = acc[bi][3] + bO1;
            float c = g_c1e[idx];
            float cn = sigf(gf) * c + sigf(gi_) * tanhf(gg);
            g_c1e[idx] = cn;
            h1b[idx] = sigf(go) * tanhf(cn);
        }
        grid_barrier(ENC_BLOCKS);
    }
}

// ---------------- decoder fused GEMM + LSTM cell ----------------
// 64(batch) x 32(unit) tile, 256 threads, each thread: 8 batch rows x 1 unit x 4 gates.
__global__ void __launch_bounds__(256) dec_cell_kernel(
    const float* __restrict__ xs, int xs_ld, int xs_sk,      // small x (7 lags) or null
    const float* __restrict__ w_ihs,                         // (1024,7)
    const float* __restrict__ xb,                            // big x (N,256) or null
    const float* __restrict__ w_ihb,                         // (1024,256)
    const float* __restrict__ h_in,                          // (N,256)
    const float* __restrict__ w_hh,                          // (1024,256)
    const float* __restrict__ b_ih, const float* __restrict__ b_hh,
    const float* __restrict__ c_in,
    float* __restrict__ h_out, float* __restrict__ c_out)
{
    __shared__ float sA[64][17];
    __shared__ float sW[128][17];
    __shared__ float sXA[64][8];
    __shared__ float sXW[128][8];

    const int t  = threadIdx.x;
    const int tg = t & 31;          // unit within tile
    const int tb = t >> 5;          // 0..7 -> batch rows tb + 8*bi
    const int b0 = blockIdx.x * 64;
    const int u0 = blockIdx.y * 32;

    float acc[8][4];
#pragma unroll
    for (int i = 0; i < 8; i++)
#pragma unroll
        for (int j = 0; j < 4; j++) acc[i][j] = 0.f;

    // ---- small-x contribution (7 lags) ----
    if (xs != nullptr) {
        if (t < 64) {
            const float* xr = xs + (long long)(b0 + t) * xs_ld;
#pragma unroll
            for (int k = 0; k < 7; k++) sXA[t][k] = xr[k * xs_sk];
        } else if (t < 192) {
            int gl = t - 64;                           // 0..127
            int grow = u0 + (gl & 31) + ((gl >> 5) << 8);
#pragma unroll
            for (int k = 0; k < 7; k++) sXW[gl][k] = w_ihs[grow * 7 + k];
        }
        __syncthreads();
#pragma unroll
        for (int k = 0; k < 7; k++) {
            float wv[4];
#pragma unroll
            for (int gi = 0; gi < 4; gi++) wv[gi] = sXW[tg + 32 * gi][k];
#pragma unroll
            for (int bi = 0; bi < 8; bi++) {
                float a = sXA[tb + 8 * bi][k];
#pragma unroll
                for (int gi = 0; gi < 4; gi++) acc[bi][gi] = fmaf(a, wv[gi], acc[bi][gi]);
            }
        }
        __syncthreads();
    }

    const int lr = t >> 2;           // 0..63
    const int lc = (t & 3) * 4;
    const int wrow0 = u0 + (lr & 31) + ((lr >> 5) << 8);          // sW rows 0..63
    const int wrow1 = u0 + ((lr + 64) & 31) + (((lr + 64) >> 5) << 8); // sW rows 64..127

    auto gemm = [&](const float* __restrict__ act, const float* __restrict__ wgt) {
        for (int k0 = 0; k0 < HH; k0 += 16) {
            float4 av = *(const float4*)(act + (long long)(b0 + lr) * HH + k0 + lc);
            float4 w0 = *(const float4*)(wgt + (long long)wrow0 * HH + k0 + lc);
            float4 w1 = *(const float4*)(wgt + (long long)wrow1 * HH + k0 + lc);
            sA[lr][lc + 0] = av.x; sA[lr][lc + 1] = av.y; sA[lr][lc + 2] = av.z; sA[lr][lc + 3] = av.w;
            sW[lr][lc + 0] = w0.x; sW[lr][lc + 1] = w0.y; sW[lr][lc + 2] = w0.z; sW[lr][lc + 3] = w0.w;
            sW[lr + 64][lc + 0] = w1.x; sW[lr + 64][lc + 1] = w1.y; sW[lr + 64][lc + 2] = w1.z; sW[lr + 64][lc + 3] = w1.w;
            __syncthreads();
#pragma unroll
            for (int kk = 0; kk < 16; kk++) {
                float w4[4], a8[8];
#pragma unroll
                for (int gi = 0; gi < 4; gi++) w4[gi] = sW[tg + 32 * gi][kk];
#pragma unroll
                for (int bi = 0; bi < 8; bi++) a8[bi] = sA[tb + 8 * bi][kk];
#pragma unroll
                for (int bi = 0; bi < 8; bi++)
#pragma unroll
                    for (int gi = 0; gi < 4; gi++)
                        acc[bi][gi] = fmaf(a8[bi], w4[gi], acc[bi][gi]);
            }
            __syncthreads();
        }
    };

    if (xb != nullptr) gemm(xb, w_ihb);
    gemm(h_in, w_hh);

    // ---- epilogue ----
    const int u = u0 + tg;
    const float bI = b_ih[u]       + b_hh[u];
    const float bF = b_ih[u + 256] + b_hh[u + 256];
    const float bG = b_ih[u + 512] + b_hh[u + 512];
    const float bO = b_ih[u + 768] + b_hh[u + 768];

#pragma unroll
    for (int bi = 0; bi < 8; bi++) {
        int b = b0 + tb + 8 * bi;
        float gi_ = acc[bi][0] + bI;
        float gf  = acc[bi][1] + bF;
        float gg  = acc[bi][2] + bG;
        float go  = acc[bi][3] + bO;
        long long idx = (long long)b * HH + u;
        float c = c_in[idx];
        float cn = sigf(gf) * c + sigf(gi_) * tanhf(gg);
        float hn = sigf(go) * tanhf(cn);
        c_out[idx] = cn;
        h_out[idx] = hn;
    }
}

// ---------------- replicate encoder state x100 + init history ----------------
__global__ void replicate_kernel() {
    int row = blockIdx.x;
    int u   = threadIdx.x;
    int b   = row / SREP;
    long long d = (long long)row * HH + u;
    long long s = (long long)b * HH + u;
    g_h0d[0][d] = g_h0e[0][s];
    g_c0d[d]    = g_c0e[s];
    g_h1d[0][d] = g_h1e[0][s];
    g_c1d[d]    = g_c1e[s];
    if (u < MAXLAG) g_hist[row * 32 + u] = g_scaled[b * TT + WIN + u];
}

// ---------------- mu/sigma head + sampling ----------------
__global__ void head_kernel(const float* __restrict__ h1,
                            const float* __restrict__ w_mu, const float* __restrict__ b_mu,
                            const float* __restrict__ w_sig, const float* __restrict__ b_sig,
                            const float* __restrict__ eps_p, int p) {
    int gid  = blockIdx.x * blockDim.x + threadIdx.x;
    int warp = gid >> 5;
    int lane = gid & 31;
    if (warp >= NDEC) return;
    const float* hr = h1 + (long long)warp * HH;
    float mu = 0.f, sg = 0.f;
#pragma unroll
    for (int k = lane; k < HH; k += 32) {
        float h = hr[k];
        mu = fmaf(h, w_mu[k], mu);
        sg = fmaf(h, w_sig[k], sg);
    }
#pragma unroll
    for (int o = 16; o > 0; o >>= 1) {
        mu += __shfl_xor_sync(0xffffffffu, mu, o);
        sg += __shfl_xor_sync(0xffffffffu, sg, o);
    }
    if (lane == 0) {
        mu += b_mu[0];
        sg += b_sig[0];
        float sp = (sg > 20.f) ? sg : log1pf(expf(sg));
        float sample = mu + sp * eps_p[warp];
        g_hist[warp * 32 + MAXLAG + p] = sample;
    }
}

// ---------------- mean over samples + denormalize ----------------
__global__ void reduce_kernel(float* __restrict__ out) {
    int gid  = blockIdx.x * blockDim.x + threadIdx.x;
    int warp = gid >> 5;
    int lane = gid & 31;
    if (warp >= BATCH * PSTEPS) return;
    int b = warp / PSTEPS;
    int p = warp % PSTEPS;
    float s = 0.f;
    for (int ss = lane; ss < SREP; ss += 32)
        s += g_hist[(b * SREP + ss) * 32 + MAXLAG + p];
#pragma unroll
    for (int o = 16; o > 0; o >>= 1) s += __shfl_xor_sync(0xffffffffu, s, o);
    if (lane == 0)
        out[b * PSTEPS + p] = s * (1.0f / (float)SREP) * g_scale[b] + g_loc[b];
}

// ---------------- launch ----------------
extern "C" void kernel_launch(void* const* d_in, const int* in_sizes, int n_in,
                              void* d_out, int out_size) {
    const float* targets = (const float*)d_in[0];
    const float* w_ih0   = (const float*)d_in[1];
    const float* w_hh0   = (const float*)d_in[2];
    const float* b_ih0   = (const float*)d_in[3];
    const float* b_hh0   = (const float*)d_in[4];
    const float* w_ih1   = (const float*)d_in[5];
    const float* w_hh1   = (const float*)d_in[6];
    const float* b_ih1   = (const float*)d_in[7];
    const float* b_hh1   = (const float*)d_in[8];
    const float* w_mu    = (const float*)d_in[9];
    const float* b_mu    = (const float*)d_in[10];
    const float* w_sigma = (const float*)d_in[11];
    const float* b_sigma = (const float*)d_in[12];
    const float* eps     = (const float*)d_in[13];
    float* out = (float*)d_out;

    float *h0d, *c0d, *h1d, *c1d, *hist;
    cudaGetSymbolAddress((void**)&h0d, g_h0d);
    cudaGetSymbolAddress((void**)&c0d, g_c0d);
    cudaGetSymbolAddress((void**)&h1d, g_h1d);
    cudaGetSymbolAddress((void**)&c1d, g_c1d);
    cudaGetSymbolAddress((void**)&hist, g_hist);

    norm_kernel<<<BATCH, 256>>>(targets);
    zero_enc_kernel<<<(BATCH * HH + 255) / 256, 256>>>();

    // ---- encoder: ONE persistent kernel, 512 steps x 2 layers ----
    encoder_kernel<<<ENC_BLOCKS, 256>>>(w_ih0, w_hh0, b_ih0, b_hh0,
                                        w_ih1, w_hh1, b_ih1, b_hh1);
    // after t=511 (odd), final state sits in parity 0

    replicate_kernel<<<NDEC, 256>>>();

    // ---- decoder: 24 steps, batch 25600 ----
    for (int p = 0; p < PSTEPS; p++) {
        int pa = p & 1, pb = pa ^ 1;
        dec_cell_kernel<<<dim3(NDEC / 64, 8), 256>>>(
            hist + (p + 6), 32, -1, w_ih0,
            nullptr, nullptr,
            h0d + pa * (NDEC * HH), w_hh0, b_ih0, b_hh0,
            c0d, h0d + pb * (NDEC * HH), c0d);
        dec_cell_kernel<<<dim3(NDEC / 64, 8), 256>>>(
            nullptr, 0, 0, nullptr,
            h0d + pb * (NDEC * HH), w_ih1,
            h1d + pa * (NDEC * HH), w_hh1, b_ih1, b_hh1,
            c1d, h1d + pb * (NDEC * HH), c1d);
        head_kernel<<<(NDEC * 32 + 255) / 256, 256>>>(
            h1d + pb * (NDEC * HH), w_mu, b_mu, w_sigma, b_sigma,
            eps + (long long)p * NDEC, p);
    }

    reduce_kernel<<<(BATCH * PSTEPS * 32 + 255) / 256, 256>>>(out);
}

// round 3
// speedup vs baseline: 1.0520x; 1.0520x over previous
#include <cuda_runtime.h>
#include <math.h>

#define HH      256
#define G4      1024
#define BATCH   256
#define WIN     512
#define TT      519     // W + MAXLAG
#define MAXLAG  7
#define SREP    100
#define NDEC    25600   // BATCH * SREP
#define PSTEPS  24
#define ESTEPS  512
#define ENC_BLOCKS 128

// ---------------- scratch (static device globals; no allocation) ----------------
__device__ __align__(128) float g_scaled[BATCH * TT];
__device__ float g_loc[BATCH];
__device__ float g_scale[BATCH];

__device__ __align__(128) float g_h0e[2][BATCH * HH];
__device__ __align__(128) float g_c0e[BATCH * HH];
__device__ __align__(128) float g_h1e[2][BATCH * HH];
__device__ __align__(128) float g_c1e[BATCH * HH];

__device__ __align__(128) float g_h0d[2][NDEC * HH];
__device__ __align__(128) float g_c0d[NDEC * HH];
__device__ __align__(128) float g_h1d[2][NDEC * HH];
__device__ __align__(128) float g_c1d[NDEC * HH];

__device__ __align__(128) float g_hist[NDEC * 32];

__device__ unsigned g_bar_count = 0;
__device__ volatile unsigned g_bar_gen = 0;

__device__ __forceinline__ float sigf(float x) { return 1.0f / (1.0f + expf(-x)); }

__device__ __forceinline__ float tf32_rna(float x) {
    float r;
    asm("cvt.rna.tf32.f32 %0, %1;\n" : "=f"(r) : "f"(x));
    return r;
}

#define MMA_TF32(c, a, b) \
    asm volatile("mma.sync.aligned.m16n8k8.row.col.f32.tf32.tf32.f32 " \
                 "{%0,%1,%2,%3}, {%4,%5,%6,%7}, {%8,%9}, {%0,%1,%2,%3};\n" \
                 : "+f"((c)[0]), "+f"((c)[1]), "+f"((c)[2]), "+f"((c)[3]) \
                 : "r"((a)[0]), "r"((a)[1]), "r"((a)[2]), "r"((a)[3]), \
                   "r"((b)[0]), "r"((b)[1]))

// ---------------- normalization ----------------
__global__ void norm_kernel(const float* __restrict__ tp) {
    int b = blockIdx.x;
    int tid = threadIdx.x;
    const float* row = tp + b * TT;

    double s = 0.0, q = 0.0;
    for (int j = tid; j < WIN; j += blockDim.x) {
        double v = (double)row[MAXLAG + j];
        s += v; q += v * v;
    }
    __shared__ double ss[256], sq[256];
    ss[tid] = s; sq[tid] = q;
    __syncthreads();
    for (int o = 128; o > 0; o >>= 1) {
        if (tid < o) { ss[tid] += ss[tid + o]; sq[tid] += sq[tid + o]; }
        __syncthreads();
    }
    __shared__ float smean, sscale;
    if (tid == 0) {
        double mean = ss[0] / (double)WIN;
        double var  = sq[0] / (double)WIN - mean * mean;
        if (var < 0.0) var = 0.0;
        float sd = (float)sqrt(var);
        float sc = (sd < 1e-10f) ? 1.0f : sd;
        smean = (float)mean; sscale = sc;
        g_loc[b] = (float)mean; g_scale[b] = sc;
    }
    __syncthreads();
    float m = smean, sc = sscale;
    for (int j = tid; j < TT; j += blockDim.x)
        g_scaled[b * TT + j] = (row[j] - m) / sc;
}

__global__ void zero_enc_kernel() {
    int i = blockIdx.x * blockDim.x + threadIdx.x;
    if (i < BATCH * HH) {
        g_h0e[0][i] = 0.f; g_c0e[i] = 0.f;
        g_h1e[0][i] = 0.f; g_c1e[i] = 0.f;
    }
}

// ---------------- software grid barrier ----------------
__device__ __forceinline__ void grid_barrier(unsigned nb) {
    __syncthreads();
    if (threadIdx.x == 0) {
        unsigned gen = g_bar_gen;
        __threadfence();
        if (atomicAdd(&g_bar_count, 1u) == nb - 1) {
            g_bar_count = 0;
            __threadfence();
            g_bar_gen = gen + 1;
        } else {
            while (g_bar_gen == gen) { }
        }
    }
    __syncthreads();
}

// ---------------- persistent encoder (unchanged, passed R2) ----------------
__global__ void __launch_bounds__(256) encoder_kernel(
    const float* __restrict__ w_ih0, const float* __restrict__ w_hh0,
    const float* __restrict__ b_ih0, const float* __restrict__ b_hh0,
    const float* __restrict__ w_ih1, const float* __restrict__ w_hh1,
    const float* __restrict__ b_ih1, const float* __restrict__ b_hh1)
{
    __shared__ float sA[32][17];
    __shared__ float sW[64][17];
    __shared__ float sXA[32][8];
    __shared__ float sXW[64][8];

    const int t  = threadIdx.x;
    const int tg = t & 15;
    const int tb = t >> 4;
    const int b0 = (blockIdx.x & 7) * 32;
    const int u0 = (blockIdx.x >> 3) * 16;

    if (t < 64) {
        int grow = u0 + (t & 15) + ((t >> 4) << 8);
#pragma unroll
        for (int k = 0; k < 7; k++) sXW[t][k] = w_ih0[grow * 7 + k];
    }

    const int u = u0 + tg;
    const float bI0 = b_ih0[u]       + b_hh0[u];
    const float bF0 = b_ih0[u + 256] + b_hh0[u + 256];
    const float bG0 = b_ih0[u + 512] + b_hh0[u + 512];
    const float bO0 = b_ih0[u + 768] + b_hh0[u + 768];
    const float bI1 = b_ih1[u]       + b_hh1[u];
    const float bF1 = b_ih1[u + 256] + b_hh1[u + 256];
    const float bG1 = b_ih1[u + 512] + b_hh1[u + 512];
    const float bO1 = b_ih1[u + 768] + b_hh1[u + 768];

    const int lr = t >> 2;
    const int lc = (t & 3) * 4;
    const int lgrow = u0 + (lr & 15) + ((lr >> 4) << 8);

    for (int step = 0; step < ESTEPS; step++) {
        const int pa = step & 1, pb = pa ^ 1;
        const float* h0a = g_h0e[pa];
        float*       h0b = g_h0e[pb];
        const float* h1a = g_h1e[pa];
        float*       h1b = g_h1e[pb];

        float acc[2][4];
#pragma unroll
        for (int i = 0; i < 2; i++)
#pragma unroll
            for (int j = 0; j < 4; j++) acc[i][j] = 0.f;

        if (t < 32) {
            const float* xr = g_scaled + (b0 + t) * TT + step + 6;
#pragma unroll
            for (int k = 0; k < 7; k++) sXA[t][k] = xr[-k];
        }
        __syncthreads();
#pragma unroll
        for (int k = 0; k < 7; k++) {
            float wv[4];
#pragma unroll
            for (int gi = 0; gi < 4; gi++) wv[gi] = sXW[tg + 16 * gi][k];
#pragma unroll
            for (int bi = 0; bi < 2; bi++) {
                float a = sXA[tb + 16 * bi][k];
#pragma unroll
                for (int gi = 0; gi < 4; gi++) acc[bi][gi] = fmaf(a, wv[gi], acc[bi][gi]);
            }
        }

        for (int k0 = 0; k0 < HH; k0 += 16) {
            __syncthreads();
            if (t < 128) {
                float4 av = __ldcg((const float4*)(h0a + (b0 + lr) * HH + k0 + lc));
                sA[lr][lc + 0] = av.x; sA[lr][lc + 1] = av.y; sA[lr][lc + 2] = av.z; sA[lr][lc + 3] = av.w;
            }
            float4 wv = *(const float4*)(w_hh0 + lgrow * HH + k0 + lc);
            sW[lr][lc + 0] = wv.x; sW[lr][lc + 1] = wv.y; sW[lr][lc + 2] = wv.z; sW[lr][lc + 3] = wv.w;
            __syncthreads();
#pragma unroll
            for (int kk = 0; kk < 16; kk++) {
                float w4[4], a2[2];
#pragma unroll
                for (int gi = 0; gi < 4; gi++) w4[gi] = sW[tg + 16 * gi][kk];
#pragma unroll
                for (int bi = 0; bi < 2; bi++) a2[bi] = sA[tb + 16 * bi][kk];
#pragma unroll
                for (int bi = 0; bi < 2; bi++)
#pragma unroll
                    for (int gi = 0; gi < 4; gi++)
                        acc[bi][gi] = fmaf(a2[bi], w4[gi], acc[bi][gi]);
            }
        }

#pragma unroll
        for (int bi = 0; bi < 2; bi++) {
            int b = b0 + tb + 16 * bi;
            int idx = b * HH + u;
            float gi_ = acc[bi][0] + bI0;
            float gf  = acc[bi][1] + bF0;
            float gg  = acc[bi][2] + bG0;
            float go  = acc[bi][3] + bO0;
            float c = g_c0e[idx];
            float cn = sigf(gf) * c + sigf(gi_) * tanhf(gg);
            g_c0e[idx] = cn;
            h0b[idx] = sigf(go) * tanhf(cn);
        }
        grid_barrier(ENC_BLOCKS);

#pragma unroll
        for (int i = 0; i < 2; i++)
#pragma unroll
            for (int j = 0; j < 4; j++) acc[i][j] = 0.f;

        for (int pass = 0; pass < 2; pass++) {
            const float* act = pass ? h1a : h0b;
            const float* wgt = pass ? w_hh1 : w_ih1;
            for (int k0 = 0; k0 < HH; k0 += 16) {
                __syncthreads();
                if (t < 128) {
                    float4 av = __ldcg((const float4*)(act + (b0 + lr) * HH + k0 + lc));
                    sA[lr][lc + 0] = av.x; sA[lr][lc + 1] = av.y; sA[lr][lc + 2] = av.z; sA[lr][lc + 3] = av.w;
                }
                float4 wv = *(const float4*)(wgt + lgrow * HH + k0 + lc);
                sW[lr][lc + 0] = wv.x; sW[lr][lc + 1] = wv.y; sW[lr][lc + 2] = wv.z; sW[lr][lc + 3] = wv.w;
                __syncthreads();
#pragma unroll
                for (int kk = 0; kk < 16; kk++) {
                    float w4[4], a2[2];
#pragma unroll
                    for (int gi = 0; gi < 4; gi++) w4[gi] = sW[tg + 16 * gi][kk];
#pragma unroll
                    for (int bi = 0; bi < 2; bi++) a2[bi] = sA[tb + 16 * bi][kk];
#pragma unroll
                    for (int bi = 0; bi < 2; bi++)
#pragma unroll
                        for (int gi = 0; gi < 4; gi++)
                            acc[bi][gi] = fmaf(a2[bi], w4[gi], acc[bi][gi]);
                }
            }
        }

#pragma unroll
        for (int bi = 0; bi < 2; bi++) {
            int b = b0 + tb + 16 * bi;
            int idx = b * HH + u;
            float gi_ = acc[bi][0] + bI1;
            float gf  = acc[bi][1] + bF1;
            float gg  = acc[bi][2] + bG1;
            float go  = acc[bi][3] + bO1;
            float c = g_c1e[idx];
            float cn = sigf(gf) * c + sigf(gi_) * tanhf(gg);
            g_c1e[idx] = cn;
            h1b[idx] = sigf(go) * tanhf(cn);
        }
        grid_barrier(ENC_BLOCKS);
    }
}

// ---------------- decoder cell: tf32 tensor-core GEMM + fused LSTM ----------------
// Block: 128 batch x 32 units (x4 gates = 128 N-cols). 8 warps: warp_m = wid&1
// (64 rows), warp_u = wid>>1 (8 units). Warp's 4 N-fragments = the 4 gate blocks
// of its 8 units, so each thread holds i,f,g,o of its cells in-register.
// 3-pass tf32 split (hi*hi + hi*lo + lo*hi) restores ~fp32 accuracy.
#define DBM 128
#define DBK 16
#define DPAD 20

__global__ void __launch_bounds__(256) dec_cell_tf32(
    const float* __restrict__ xs,        // lag base (g_hist + p + 6) or null
    const float* __restrict__ w_ihs,     // (1024,7)
    const float* __restrict__ xb,        // big x (N,256) or null
    const float* __restrict__ w_ihb,     // (1024,256)
    const float* __restrict__ h_in,      // (N,256)
    const float* __restrict__ w_hh,      // (1024,256)
    const float* __restrict__ b_ih, const float* __restrict__ b_hh,
    const float* __restrict__ c_in,
    float* __restrict__ h_out, float* __restrict__ c_out)
{
    __shared__ float sAhi[DBM][DPAD];
    __shared__ float sAlo[DBM][DPAD];
    __shared__ float sBhi[DBM][DPAD];
    __shared__ float sBlo[DBM][DPAD];
    __shared__ float sBias[128];

    const int t    = threadIdx.x;
    const int lane = t & 31;
    const int wid  = t >> 5;
    const int m0w  = (wid & 1) * 64;
    const int u0w  = (wid >> 1) * 8;
    const int b0   = blockIdx.x * DBM;
    const int u0   = blockIdx.y * 32;

    // gate-row this thread loads for weight tiles / bias
    const int lrow = t >> 1;
    const int lc0  = (t & 1) * 8;
    const int lgrow = u0 + (lrow & 31) + ((lrow >> 5) << 8);

    if (t < 128) {
        int grow = u0 + (t & 31) + ((t >> 5) << 8);
        sBias[t] = b_ih[grow] + b_hh[grow];
    }

    float acc[4][4][4];
#pragma unroll
    for (int mi = 0; mi < 4; mi++)
#pragma unroll
        for (int g = 0; g < 4; g++)
#pragma unroll
            for (int r = 0; r < 4; r++) acc[mi][g][r] = 0.f;

    const int qr = lane >> 2;       // 0..7
    const int qc = lane & 3;        // 0..3

    // -------- compute over one loaded K-16 chunk --------
    auto compute_chunk = [&]() {
#pragma unroll
        for (int ks = 0; ks < 2; ks++) {
            const int kk = ks * 8;
            unsigned ahi[4][4], alo[4][4];
#pragma unroll
            for (int mi = 0; mi < 4; mi++) {
                int r  = m0w + mi * 16 + qr;
                int c  = kk + qc;
                ahi[mi][0] = __float_as_uint(sAhi[r][c]);
                ahi[mi][1] = __float_as_uint(sAhi[r + 8][c]);
                ahi[mi][2] = __float_as_uint(sAhi[r][c + 4]);
                ahi[mi][3] = __float_as_uint(sAhi[r + 8][c + 4]);
                alo[mi][0] = __float_as_uint(sAlo[r][c]);
                alo[mi][1] = __float_as_uint(sAlo[r + 8][c]);
                alo[mi][2] = __float_as_uint(sAlo[r][c + 4]);
                alo[mi][3] = __float_as_uint(sAlo[r + 8][c + 4]);
            }
            unsigned bhi[4][2], blo[4][2];
#pragma unroll
            for (int g = 0; g < 4; g++) {
                int br = g * 32 + u0w + qr;
                int c  = kk + qc;
                bhi[g][0] = __float_as_uint(sBhi[br][c]);
                bhi[g][1] = __float_as_uint(sBhi[br][c + 4]);
                blo[g][0] = __float_as_uint(sBlo[br][c]);
                blo[g][1] = __float_as_uint(sBlo[br][c + 4]);
            }
#pragma unroll
            for (int mi = 0; mi < 4; mi++)
#pragma unroll
                for (int g = 0; g < 4; g++) {
                    MMA_TF32(acc[mi][g], ahi[mi], bhi[g]);
                    MMA_TF32(acc[mi][g], ahi[mi], blo[g]);
                    MMA_TF32(acc[mi][g], alo[mi], bhi[g]);
                }
        }
    };

    auto split_store_a = [&](int col, float v) {
        float h_ = tf32_rna(v);
        sAhi[lrow][col] = h_;
        sAlo[lrow][col] = tf32_rna(v - h_);
    };
    auto split_store_b = [&](int col, float v) {
        float h_ = tf32_rna(v);
        sBhi[lrow][col] = h_;
        sBlo[lrow][col] = tf32_rna(v - h_);
    };

    // -------- lag chunk (K=7 zero-padded to 16) --------
    if (xs != nullptr) {
        __syncthreads();
#pragma unroll
        for (int cc = 0; cc < 8; cc++) {
            int k = lc0 + cc;
            float va = (k < 7) ? xs[(b0 + lrow) * 32 - k] : 0.f;
            float vb = (k < 7) ? w_ihs[lgrow * 7 + k] : 0.f;
            split_store_a(k, va);
            split_store_b(k, vb);
        }
        __syncthreads();
        compute_chunk();
    }

    // -------- dense K=256 segments --------
    auto gemm_segment = [&](const float* __restrict__ act, const float* __restrict__ wgt) {
        for (int k0 = 0; k0 < HH; k0 += DBK) {
            __syncthreads();
            const float* ar = act + (long long)(b0 + lrow) * HH + k0 + lc0;
            float4 a0 = *(const float4*)(ar);
            float4 a1 = *(const float4*)(ar + 4);
            const float* wr = wgt + (long long)lgrow * HH + k0 + lc0;
            float4 w0 = *(const float4*)(wr);
            float4 w1 = *(const float4*)(wr + 4);
            split_store_a(lc0 + 0, a0.x); split_store_a(lc0 + 1, a0.y);
            split_store_a(lc0 + 2, a0.z); split_store_a(lc0 + 3, a0.w);
            split_store_a(lc0 + 4, a1.x); split_store_a(lc0 + 5, a1.y);
            split_store_a(lc0 + 6, a1.z); split_store_a(lc0 + 7, a1.w);
            split_store_b(lc0 + 0, w0.x); split_store_b(lc0 + 1, w0.y);
            split_store_b(lc0 + 2, w0.z); split_store_b(lc0 + 3, w0.w);
            split_store_b(lc0 + 4, w1.x); split_store_b(lc0 + 5, w1.y);
            split_store_b(lc0 + 6, w1.z); split_store_b(lc0 + 7, w1.w);
            __syncthreads();
            compute_chunk();
        }
    };

    if (xb != nullptr) gemm_segment(xb, w_ihb);
    gemm_segment(h_in, w_hh);

    // -------- epilogue: fused LSTM nonlinearity --------
#pragma unroll
    for (int mi = 0; mi < 4; mi++) {
        int rbase = b0 + m0w + mi * 16 + qr;
#pragma unroll
        for (int half = 0; half < 2; half++) {
            int row = rbase + half * 8;
#pragma unroll
            for (int j = 0; j < 2; j++) {
                int ucol = 2 * qc + j;
                int u = u0 + u0w + ucol;
                int ci = half * 2 + j;
                float gi_ = acc[mi][0][ci] + sBias[ 0 + u0w + ucol];
                float gf  = acc[mi][1][ci] + sBias[32 + u0w + ucol];
                float gg  = acc[mi][2][ci] + sBias[64 + u0w + ucol];
                float go  = acc[mi][3][ci] + sBias[96 + u0w + ucol];
                long long idx = (long long)row * HH + u;
                float c = c_in[idx];
                float cn = sigf(gf) * c + sigf(gi_) * tanhf(gg);
                float hn = sigf(go) * tanhf(cn);
                c_out[idx] = cn;
                h_out[idx] = hn;
            }
        }
    }
}

// ---------------- replicate encoder state x100 + init history ----------------
__global__ void replicate_kernel() {
    int row = blockIdx.x;
    int u   = threadIdx.x;
    int b   = row / SREP;
    long long d = (long long)row * HH + u;
    long long s = (long long)b * HH + u;
    g_h0d[0][d] = g_h0e[0][s];
    g_c0d[d]    = g_c0e[s];
    g_h1d[0][d] = g_h1e[0][s];
    g_c1d[d]    = g_c1e[s];
    if (u < MAXLAG) g_hist[row * 32 + u] = g_scaled[b * TT + WIN + u];
}

// ---------------- mu/sigma head + sampling ----------------
__global__ void head_kernel(const float* __restrict__ h1,
                            const float* __restrict__ w_mu, const float* __restrict__ b_mu,
                            const float* __restrict__ w_sig, const float* __restrict__ b_sig,
                            const float* __restrict__ eps_p, int p) {
    int gid  = blockIdx.x * blockDim.x + threadIdx.x;
    int warp = gid >> 5;
    int lane = gid & 31;
    if (warp >= NDEC) return;
    const float* hr = h1 + (long long)warp * HH;
    float mu = 0.f, sg = 0.f;
#pragma unroll
    for (int k = lane; k < HH; k += 32) {
        float h = hr[k];
        mu = fmaf(h, w_mu[k], mu);
        sg = fmaf(h, w_sig[k], sg);
    }
#pragma unroll
    for (int o = 16; o > 0; o >>= 1) {
        mu += __shfl_xor_sync(0xffffffffu, mu, o);
        sg += __shfl_xor_sync(0xffffffffu, sg, o);
    }
    if (lane == 0) {
        mu += b_mu[0];
        sg += b_sig[0];
        float sp = (sg > 20.f) ? sg : log1pf(expf(sg));
        float sample = mu + sp * eps_p[warp];
        g_hist[warp * 32 + MAXLAG + p] = sample;
    }
}

// ---------------- mean over samples + denormalize ----------------
__global__ void reduce_kernel(float* __restrict__ out) {
    int gid  = blockIdx.x * blockDim.x + threadIdx.x;
    int warp = gid >> 5;
    int lane = gid & 31;
    if (warp >= BATCH * PSTEPS) return;
    int b = warp / PSTEPS;
    int p = warp % PSTEPS;
    float s = 0.f;
    for (int ss = lane; ss < SREP; ss += 32)
        s += g_hist[(b * SREP + ss) * 32 + MAXLAG + p];
#pragma unroll
    for (int o = 16; o > 0; o >>= 1) s += __shfl_xor_sync(0xffffffffu, s, o);
    if (lane == 0)
        out[b * PSTEPS + p] = s * (1.0f / (float)SREP) * g_scale[b] + g_loc[b];
}

// ---------------- launch ----------------
extern "C" void kernel_launch(void* const* d_in, const int* in_sizes, int n_in,
                              void* d_out, int out_size) {
    const float* targets = (const float*)d_in[0];
    const float* w_ih0   = (const float*)d_in[1];
    const float* w_hh0   = (const float*)d_in[2];
    const float* b_ih0   = (const float*)d_in[3];
    const float* b_hh0   = (const float*)d_in[4];
    const float* w_ih1   = (const float*)d_in[5];
    const float* w_hh1   = (const float*)d_in[6];
    const float* b_ih1   = (const float*)d_in[7];
    const float* b_hh1   = (const float*)d_in[8];
    const float* w_mu    = (const float*)d_in[9];
    const float* b_mu    = (const float*)d_in[10];
    const float* w_sigma = (const float*)d_in[11];
    const float* b_sigma = (const float*)d_in[12];
    const float* eps     = (const float*)d_in[13];
    float* out = (float*)d_out;

    float *h0d, *c0d, *h1d, *c1d, *hist;
    cudaGetSymbolAddress((void**)&h0d, g_h0d);
    cudaGetSymbolAddress((void**)&c0d, g_c0d);
    cudaGetSymbolAddress((void**)&h1d, g_h1d);
    cudaGetSymbolAddress((void**)&c1d, g_c1d);
    cudaGetSymbolAddress((void**)&hist, g_hist);

    norm_kernel<<<BATCH, 256>>>(targets);
    zero_enc_kernel<<<(BATCH * HH + 255) / 256, 256>>>();

    encoder_kernel<<<ENC_BLOCKS, 256>>>(w_ih0, w_hh0, b_ih0, b_hh0,
                                        w_ih1, w_hh1, b_ih1, b_hh1);

    replicate_kernel<<<NDEC, 256>>>();

    for (int p = 0; p < PSTEPS; p++) {
        int pa = p & 1, pb = pa ^ 1;
        // layer 0: lags + h0 @ w_hh0^T
        dec_cell_tf32<<<dim3(NDEC / DBM, 8), 256>>>(
            hist + p + 6, w_ih0,
            nullptr, nullptr,
            h0d + pa * (NDEC * HH), w_hh0, b_ih0, b_hh0,
            c0d, h0d + pb * (NDEC * HH), c0d);
        // layer 1: h0_new @ w_ih1^T + h1 @ w_hh1^T
        dec_cell_tf32<<<dim3(NDEC / DBM, 8), 256>>>(
            nullptr, nullptr,
            h0d + pb * (NDEC * HH), w_ih1,
            h1d + pa * (NDEC * HH), w_hh1, b_ih1, b_hh1,
            c1d, h1d + pb * (NDEC * HH), c1d);
        head_kernel<<<(NDEC * 32 + 255) / 256, 256>>>(
            h1d + pb * (NDEC * HH), w_mu, b_mu, w_sigma, b_sigma,
            eps + (long long)p * NDEC, p);
    }

    reduce_kernel<<<(BATCH * PSTEPS * 32 + 255) / 256, 256>>>(out);
}

// round 4
// speedup vs baseline: 1.2501x; 1.1883x over previous
#include <cuda_runtime.h>
#include <math.h>

#define HH      256
#define G4      1024
#define BATCH   256
#define WIN     512
#define TT      519     // W + MAXLAG
#define MAXLAG  7
#define SREP    100
#define NDEC    25600   // BATCH * SREP
#define PSTEPS  24
#define ESTEPS  512
#define ENC_BLOCKS 128

// encoder dynamic smem layout (floats)
#define WSTR 260                       // padded K-stride for weight tiles
#define OFF_W0   0
#define OFF_WI1  (64 * WSTR)
#define OFF_WH1  (2 * 64 * WSTR)
#define OFF_SH   (3 * 64 * WSTR)       // 2 x 32 x 20 h chunk buffers
#define OFF_SXW  (OFF_SH + 2 * 32 * 20)
#define OFF_SXA  (OFF_SXW + 64 * 8)
#define ENC_SMEM_FLOATS (OFF_SXA + 32 * 8)
#define ENC_SMEM_BYTES  (ENC_SMEM_FLOATS * 4)

// ---------------- scratch (static device globals; no allocation) ----------------
__device__ __align__(128) float g_scaled[BATCH * TT];
__device__ float g_loc[BATCH];
__device__ float g_scale[BATCH];

__device__ __align__(128) float g_h0e[2][BATCH * HH];
__device__ __align__(128) float g_c0e[BATCH * HH];
__device__ __align__(128) float g_h1e[2][BATCH * HH];
__device__ __align__(128) float g_c1e[BATCH * HH];

__device__ __align__(128) float g_h0d[2][NDEC * HH];
__device__ __align__(128) float g_c0d[NDEC * HH];
__device__ __align__(128) float g_h1d[2][NDEC * HH];
__device__ __align__(128) float g_c1d[NDEC * HH];

__device__ __align__(128) float g_hist[NDEC * 32];

__device__ unsigned g_bar_count = 0;
__device__ volatile unsigned g_bar_gen = 0;

__device__ __forceinline__ float sigf(float x) { return 1.0f / (1.0f + expf(-x)); }

__device__ __forceinline__ float tf32_rna(float x) {
    float r;
    asm("cvt.rna.tf32.f32 %0, %1;\n" : "=f"(r) : "f"(x));
    return r;
}

#define MMA_TF32(c, a, b) \
    asm volatile("mma.sync.aligned.m16n8k8.row.col.f32.tf32.tf32.f32 " \
                 "{%0,%1,%2,%3}, {%4,%5,%6,%7}, {%8,%9}, {%0,%1,%2,%3};\n" \
                 : "+f"((c)[0]), "+f"((c)[1]), "+f"((c)[2]), "+f"((c)[3]) \
                 : "r"((a)[0]), "r"((a)[1]), "r"((a)[2]), "r"((a)[3]), \
                   "r"((b)[0]), "r"((b)[1]))

// ---------------- normalization ----------------
__global__ void norm_kernel(const float* __restrict__ tp) {
    int b = blockIdx.x;
    int tid = threadIdx.x;
    const float* row = tp + b * TT;

    double s = 0.0, q = 0.0;
    for (int j = tid; j < WIN; j += blockDim.x) {
        double v = (double)row[MAXLAG + j];
        s += v; q += v * v;
    }
    __shared__ double ss[256], sq[256];
    ss[tid] = s; sq[tid] = q;
    __syncthreads();
    for (int o = 128; o > 0; o >>= 1) {
        if (tid < o) { ss[tid] += ss[tid + o]; sq[tid] += sq[tid + o]; }
        __syncthreads();
    }
    __shared__ float smean, sscale;
    if (tid == 0) {
        double mean = ss[0] / (double)WIN;
        double var  = sq[0] / (double)WIN - mean * mean;
        if (var < 0.0) var = 0.0;
        float sd = (float)sqrt(var);
        float sc = (sd < 1e-10f) ? 1.0f : sd;
        smean = (float)mean; sscale = sc;
        g_loc[b] = (float)mean; g_scale[b] = sc;
    }
    __syncthreads();
    float m = smean, sc = sscale;
    for (int j = tid; j < TT; j += blockDim.x)
        g_scaled[b * TT + j] = (row[j] - m) / sc;
}

__global__ void zero_enc_kernel() {
    int i = blockIdx.x * blockDim.x + threadIdx.x;
    if (i < BATCH * HH) {
        g_h0e[0][i] = 0.f; g_c0e[i] = 0.f;
        g_h1e[0][i] = 0.f; g_c1e[i] = 0.f;
    }
}

// ---------------- software grid barrier ----------------
__device__ __forceinline__ void grid_barrier(unsigned nb) {
    __syncthreads();
    if (threadIdx.x == 0) {
        unsigned gen = g_bar_gen;
        __threadfence();
        if (atomicAdd(&g_bar_count, 1u) == nb - 1) {
            g_bar_count = 0;
            __threadfence();
            g_bar_gen = gen + 1;
        } else {
            while (g_bar_gen == gen) { }
        }
    }
    __syncthreads();
}

// ---------------- persistent encoder v2: weights in SMEM, h double-buffered ----------------
// 128 blocks x 256 threads; block owns 32 batch rows x 16 units (64 gate-rows).
// Weight slices (w_hh0, w_ih1, w_hh1 : 64x256 each) live in dynamic smem for the
// whole kernel. Per step only h tiles stream from L2, prefetched while computing.
__global__ void __launch_bounds__(256) encoder_kernel(
    const float* __restrict__ w_ih0, const float* __restrict__ w_hh0,
    const float* __restrict__ b_ih0, const float* __restrict__ b_hh0,
    const float* __restrict__ w_ih1, const float* __restrict__ w_hh1,
    const float* __restrict__ b_ih1, const float* __restrict__ b_hh1)
{
    extern __shared__ float es[];
    float* W0  = es + OFF_W0;
    float* WI1 = es + OFF_WI1;
    float* WH1 = es + OFF_WH1;
    float* SH  = es + OFF_SH;     // [2][32][20]
    float* SXW = es + OFF_SXW;    // [64][8]
    float* SXA = es + OFF_SXA;    // [32][8]

    const int t  = threadIdx.x;
    const int tg = t & 15;
    const int tb = t >> 4;
    const int b0 = (blockIdx.x & 7) * 32;
    const int u0 = (blockIdx.x >> 3) * 16;

    // ---- load weight slices into smem once ----
#pragma unroll
    for (int i = 0; i < 16; i++) {
        int idx = t + i * 256;
        int r   = idx >> 6;         // 0..63
        int c4  = idx & 63;         // 0..63 (float4 col)
        int grow = u0 + (r & 15) + ((r >> 4) << 8);
        float4 v0 = *(const float4*)(w_hh0 + grow * 256 + c4 * 4);
        *(float4*)(W0 + r * WSTR + c4 * 4) = v0;
        float4 v1 = *(const float4*)(w_ih1 + grow * 256 + c4 * 4);
        *(float4*)(WI1 + r * WSTR + c4 * 4) = v1;
        float4 v2 = *(const float4*)(w_hh1 + grow * 256 + c4 * 4);
        *(float4*)(WH1 + r * WSTR + c4 * 4) = v2;
    }
    if (t < 64) {
        int grow = u0 + (t & 15) + ((t >> 4) << 8);
#pragma unroll
        for (int k = 0; k < 7; k++) SXW[t * 8 + k] = w_ih0[grow * 7 + k];
    }

    const int u = u0 + tg;
    const float bI0 = b_ih0[u]       + b_hh0[u];
    const float bF0 = b_ih0[u + 256] + b_hh0[u + 256];
    const float bG0 = b_ih0[u + 512] + b_hh0[u + 512];
    const float bO0 = b_ih0[u + 768] + b_hh0[u + 768];
    const float bI1 = b_ih1[u]       + b_hh1[u];
    const float bF1 = b_ih1[u + 256] + b_hh1[u + 256];
    const float bG1 = b_ih1[u + 512] + b_hh1[u + 512];
    const float bO1 = b_ih1[u + 768] + b_hh1[u + 768];
    __syncthreads();

    const int prow = t >> 3;        // 0..31 (h prefetch row)
    const int pcol = (t & 7) * 2;   // 0..14 (float2 col within 16-chunk)

    // GEMM over K=256 from global 'act' (L2, __ldcg) against smem weight slice.
    auto run_gemm = [&](const float* act, const float* wsm, float (&acc)[2][4]) {
        // stage chunk 0
        float2 p0 = __ldcg((const float2*)(act + (b0 + prow) * HH + pcol));
        SH[prow * 20 + pcol]     = p0.x;
        SH[prow * 20 + pcol + 1] = p0.y;
        __syncthreads();
        for (int kc = 0; kc < 16; kc++) {
            float2 nxt;
            const bool have = (kc + 1) < 16;
            if (have)
                nxt = __ldcg((const float2*)(act + (b0 + prow) * HH + (kc + 1) * 16 + pcol));
            const float* hb = SH + (kc & 1) * 640;
            const float* wb = wsm + kc * 16;
#pragma unroll
            for (int g4 = 0; g4 < 4; g4++) {
                int kl = g4 * 4;
                float4 wv[4], av[2];
#pragma unroll
                for (int gi = 0; gi < 4; gi++)
                    wv[gi] = *(const float4*)(wb + (tg + 16 * gi) * WSTR + kl);
#pragma unroll
                for (int bi = 0; bi < 2; bi++)
                    av[bi] = *(const float4*)(hb + (tb + 16 * bi) * 20 + kl);
#pragma unroll
                for (int bi = 0; bi < 2; bi++) {
#pragma unroll
                    for (int gi = 0; gi < 4; gi++) {
                        acc[bi][gi] = fmaf(av[bi].x, wv[gi].x, acc[bi][gi]);
                        acc[bi][gi] = fmaf(av[bi].y, wv[gi].y, acc[bi][gi]);
                        acc[bi][gi] = fmaf(av[bi].z, wv[gi].z, acc[bi][gi]);
                        acc[bi][gi] = fmaf(av[bi].w, wv[gi].w, acc[bi][gi]);
                    }
                }
            }
            if (have) {
                float* d = SH + ((kc + 1) & 1) * 640 + prow * 20 + pcol;
                d[0] = nxt.x; d[1] = nxt.y;
            }
            __syncthreads();
        }
    };

    for (int step = 0; step < ESTEPS; step++) {
        const int pa = step & 1, pb = pa ^ 1;
        const float* h0a = g_h0e[pa];
        float*       h0b = g_h0e[pb];
        const float* h1a = g_h1e[pa];
        float*       h1b = g_h1e[pb];

        // lag inputs for this step (latency hidden behind the layer-0 GEMM)
        if (t < 32) {
            const float* xr = g_scaled + (b0 + t) * TT + step + 6;
#pragma unroll
            for (int k = 0; k < 7; k++) SXA[t * 8 + k] = xr[-k];
        }

        // ===== layer 0 =====
        float acc[2][4];
#pragma unroll
        for (int i = 0; i < 2; i++)
#pragma unroll
            for (int j = 0; j < 4; j++) acc[i][j] = 0.f;

        run_gemm(h0a, W0, acc);

        // lag contribution (SXA visible via gemm's syncthreads)
#pragma unroll
        for (int k = 0; k < 7; k++) {
            float wv[4];
#pragma unroll
            for (int gi = 0; gi < 4; gi++) wv[gi] = SXW[(tg + 16 * gi) * 8 + k];
#pragma unroll
            for (int bi = 0; bi < 2; bi++) {
                float a = SXA[(tb + 16 * bi) * 8 + k];
#pragma unroll
                for (int gi = 0; gi < 4; gi++) acc[bi][gi] = fmaf(a, wv[gi], acc[bi][gi]);
            }
        }

#pragma unroll
        for (int bi = 0; bi < 2; bi++) {
            int b = b0 + tb + 16 * bi;
            int idx = b * HH + u;
            float gi_ = acc[bi][0] + bI0;
            float gf  = acc[bi][1] + bF0;
            float gg  = acc[bi][2] + bG0;
            float go  = acc[bi][3] + bO0;
            float c = g_c0e[idx];
            float cn = sigf(gf) * c + sigf(gi_) * tanhf(gg);
            g_c0e[idx] = cn;
            h0b[idx] = sigf(go) * tanhf(cn);
        }
        grid_barrier(ENC_BLOCKS);

        // ===== layer 1 =====
#pragma unroll
        for (int i = 0; i < 2; i++)
#pragma unroll
            for (int j = 0; j < 4; j++) acc[i][j] = 0.f;

        run_gemm(h0b, WI1, acc);
        run_gemm(h1a, WH1, acc);

#pragma unroll
        for (int bi = 0; bi < 2; bi++) {
            int b = b0 + tb + 16 * bi;
            int idx = b * HH + u;
            float gi_ = acc[bi][0] + bI1;
            float gf  = acc[bi][1] + bF1;
            float gg  = acc[bi][2] + bG1;
            float go  = acc[bi][3] + bO1;
            float c = g_c1e[idx];
            float cn = sigf(gf) * c + sigf(gi_) * tanhf(gg);
            g_c1e[idx] = cn;
            h1b[idx] = sigf(go) * tanhf(cn);
        }
        grid_barrier(ENC_BLOCKS);
    }
}

// ---------------- decoder cell: tf32 tensor-core GEMM + fused LSTM (passed R3) ----------------
#define DBM 128
#define DBK 16
#define DPAD 20

__global__ void __launch_bounds__(256) dec_cell_tf32(
    const float* __restrict__ xs,
    const float* __restrict__ w_ihs,
    const float* __restrict__ xb,
    const float* __restrict__ w_ihb,
    const float* __restrict__ h_in,
    const float* __restrict__ w_hh,
    const float* __restrict__ b_ih, const float* __restrict__ b_hh,
    const float* __restrict__ c_in,
    float* __restrict__ h_out, float* __restrict__ c_out)
{
    __shared__ float sAhi[DBM][DPAD];
    __shared__ float sAlo[DBM][DPAD];
    __shared__ float sBhi[DBM][DPAD];
    __shared__ float sBlo[DBM][DPAD];
    __shared__ float sBias[128];

    const int t    = threadIdx.x;
    const int lane = t & 31;
    const int wid  = t >> 5;
    const int m0w  = (wid & 1) * 64;
    const int u0w  = (wid >> 1) * 8;
    const int b0   = blockIdx.x * DBM;
    const int u0   = blockIdx.y * 32;

    const int lrow = t >> 1;
    const int lc0  = (t & 1) * 8;
    const int lgrow = u0 + (lrow & 31) + ((lrow >> 5) << 8);

    if (t < 128) {
        int grow = u0 + (t & 31) + ((t >> 5) << 8);
        sBias[t] = b_ih[grow] + b_hh[grow];
    }

    float acc[4][4][4];
#pragma unroll
    for (int mi = 0; mi < 4; mi++)
#pragma unroll
        for (int g = 0; g < 4; g++)
#pragma unroll
            for (int r = 0; r < 4; r++) acc[mi][g][r] = 0.f;

    const int qr = lane >> 2;
    const int qc = lane & 3;

    auto compute_chunk = [&]() {
#pragma unroll
        for (int ks = 0; ks < 2; ks++) {
            const int kk = ks * 8;
            unsigned ahi[4][4], alo[4][4];
#pragma unroll
            for (int mi = 0; mi < 4; mi++) {
                int r  = m0w + mi * 16 + qr;
                int c  = kk + qc;
                ahi[mi][0] = __float_as_uint(sAhi[r][c]);
                ahi[mi][1] = __float_as_uint(sAhi[r + 8][c]);
                ahi[mi][2] = __float_as_uint(sAhi[r][c + 4]);
                ahi[mi][3] = __float_as_uint(sAhi[r + 8][c + 4]);
                alo[mi][0] = __float_as_uint(sAlo[r][c]);
                alo[mi][1] = __float_as_uint(sAlo[r + 8][c]);
                alo[mi][2] = __float_as_uint(sAlo[r][c + 4]);
                alo[mi][3] = __float_as_uint(sAlo[r + 8][c + 4]);
            }
            unsigned bhi[4][2], blo[4][2];
#pragma unroll
            for (int g = 0; g < 4; g++) {
                int br = g * 32 + u0w + qr;
                int c  = kk + qc;
                bhi[g][0] = __float_as_uint(sBhi[br][c]);
                bhi[g][1] = __float_as_uint(sBhi[br][c + 4]);
                blo[g][0] = __float_as_uint(sBlo[br][c]);
                blo[g][1] = __float_as_uint(sBlo[br][c + 4]);
            }
#pragma unroll
            for (int mi = 0; mi < 4; mi++)
#pragma unroll
                for (int g = 0; g < 4; g++) {
                    MMA_TF32(acc[mi][g], ahi[mi], bhi[g]);
                    MMA_TF32(acc[mi][g], ahi[mi], blo[g]);
                    MMA_TF32(acc[mi][g], alo[mi], bhi[g]);
                }
        }
    };

    auto split_store_a = [&](int col, float v) {
        float h_ = tf32_rna(v);
        sAhi[lrow][col] = h_;
        sAlo[lrow][col] = tf32_rna(v - h_);
    };
    auto split_store_b = [&](int col, float v) {
        float h_ = tf32_rna(v);
        sBhi[lrow][col] = h_;
        sBlo[lrow][col] = tf32_rna(v - h_);
    };

    if (xs != nullptr) {
        __syncthreads();
#pragma unroll
        for (int cc = 0; cc < 8; cc++) {
            int k = lc0 + cc;
            float va = (k < 7) ? xs[(b0 + lrow) * 32 - k] : 0.f;
            float vb = (k < 7) ? w_ihs[lgrow * 7 + k] : 0.f;
            split_store_a(k, va);
            split_store_b(k, vb);
        }
        __syncthreads();
        compute_chunk();
    }

    auto gemm_segment = [&](const float* __restrict__ act, const float* __restrict__ wgt) {
        for (int k0 = 0; k0 < HH; k0 += DBK) {
            __syncthreads();
            const float* ar = act + (long long)(b0 + lrow) * HH + k0 + lc0;
            float4 a0 = *(const float4*)(ar);
            float4 a1 = *(const float4*)(ar + 4);
            const float* wr = wgt + (long long)lgrow * HH + k0 + lc0;
            float4 w0 = *(const float4*)(wr);
            float4 w1 = *(const float4*)(wr + 4);
            split_store_a(lc0 + 0, a0.x); split_store_a(lc0 + 1, a0.y);
            split_store_a(lc0 + 2, a0.z); split_store_a(lc0 + 3, a0.w);
            split_store_a(lc0 + 4, a1.x); split_store_a(lc0 + 5, a1.y);
            split_store_a(lc0 + 6, a1.z); split_store_a(lc0 + 7, a1.w);
            split_store_b(lc0 + 0, w0.x); split_store_b(lc0 + 1, w0.y);
            split_store_b(lc0 + 2, w0.z); split_store_b(lc0 + 3, w0.w);
            split_store_b(lc0 + 4, w1.x); split_store_b(lc0 + 5, w1.y);
            split_store_b(lc0 + 6, w1.z); split_store_b(lc0 + 7, w1.w);
            __syncthreads();
            compute_chunk();
        }
    };

    if (xb != nullptr) gemm_segment(xb, w_ihb);
    gemm_segment(h_in, w_hh);

#pragma unroll
    for (int mi = 0; mi < 4; mi++) {
        int rbase = b0 + m0w + mi * 16 + qr;
#pragma unroll
        for (int half = 0; half < 2; half++) {
            int row = rbase + half * 8;
#pragma unroll
            for (int j = 0; j < 2; j++) {
                int ucol = 2 * qc + j;
                int u = u0 + u0w + ucol;
                int ci = half * 2 + j;
                float gi_ = acc[mi][0][ci] + sBias[ 0 + u0w + ucol];
                float gf  = acc[mi][1][ci] + sBias[32 + u0w + ucol];
                float gg  = acc[mi][2][ci] + sBias[64 + u0w + ucol];
                float go  = acc[mi][3][ci] + sBias[96 + u0w + ucol];
                long long idx = (long long)row * HH + u;
                float c = c_in[idx];
                float cn = sigf(gf) * c + sigf(gi_) * tanhf(gg);
                float hn = sigf(go) * tanhf(cn);
                c_out[idx] = cn;
                h_out[idx] = hn;
            }
        }
    }
}

// ---------------- replicate encoder state x100 + init history ----------------
__global__ void replicate_kernel() {
    int row = blockIdx.x;
    int u   = threadIdx.x;
    int b   = row / SREP;
    long long d = (long long)row * HH + u;
    long long s = (long long)b * HH + u;
    g_h0d[0][d] = g_h0e[0][s];
    g_c0d[d]    = g_c0e[s];
    g_h1d[0][d] = g_h1e[0][s];
    g_c1d[d]    = g_c1e[s];
    if (u < MAXLAG) g_hist[row * 32 + u] = g_scaled[b * TT + WIN + u];
}

// ---------------- mu/sigma head + sampling ----------------
__global__ void head_kernel(const float* __restrict__ h1,
                            const float* __restrict__ w_mu, const float* __restrict__ b_mu,
                            const float* __restrict__ w_sig, const float* __restrict__ b_sig,
                            const float* __restrict__ eps_p, int p) {
    int gid  = blockIdx.x * blockDim.x + threadIdx.x;
    int warp = gid >> 5;
    int lane = gid & 31;
    if (warp >= NDEC) return;
    const float* hr = h1 + (long long)warp * HH;
    float mu = 0.f, sg = 0.f;
#pragma unroll
    for (int k = lane; k < HH; k += 32) {
        float h = hr[k];
        mu = fmaf(h, w_mu[k], mu);
        sg = fmaf(h, w_sig[k], sg);
    }
#pragma unroll
    for (int o = 16; o > 0; o >>= 1) {
        mu += __shfl_xor_sync(0xffffffffu, mu, o);
        sg += __shfl_xor_sync(0xffffffffu, sg, o);
    }
    if (lane == 0) {
        mu += b_mu[0];
        sg += b_sig[0];
        float sp = (sg > 20.f) ? sg : log1pf(expf(sg));
        float sample = mu + sp * eps_p[warp];
        g_hist[warp * 32 + MAXLAG + p] = sample;
    }
}

// ---------------- mean over samples + denormalize ----------------
__global__ void reduce_kernel(float* __restrict__ out) {
    int gid  = blockIdx.x * blockDim.x + threadIdx.x;
    int warp = gid >> 5;
    int lane = gid & 31;
    if (warp >= BATCH * PSTEPS) return;
    int b = warp / PSTEPS;
    int p = warp % PSTEPS;
    float s = 0.f;
    for (int ss = lane; ss < SREP; ss += 32)
        s += g_hist[(b * SREP + ss) * 32 + MAXLAG + p];
#pragma unroll
    for (int o = 16; o > 0; o >>= 1) s += __shfl_xor_sync(0xffffffffu, s, o);
    if (lane == 0)
        out[b * PSTEPS + p] = s * (1.0f / (float)SREP) * g_scale[b] + g_loc[b];
}

// ---------------- launch ----------------
extern "C" void kernel_launch(void* const* d_in, const int* in_sizes, int n_in,
                              void* d_out, int out_size) {
    const float* targets = (const float*)d_in[0];
    const float* w_ih0   = (const float*)d_in[1];
    const float* w_hh0   = (const float*)d_in[2];
    const float* b_ih0   = (const float*)d_in[3];
    const float* b_hh0   = (const float*)d_in[4];
    const float* w_ih1   = (const float*)d_in[5];
    const float* w_hh1   = (const float*)d_in[6];
    const float* b_ih1   = (const float*)d_in[7];
    const float* b_hh1   = (const float*)d_in[8];
    const float* w_mu    = (const float*)d_in[9];
    const float* b_mu    = (const float*)d_in[10];
    const float* w_sigma = (const float*)d_in[11];
    const float* b_sigma = (const float*)d_in[12];
    const float* eps     = (const float*)d_in[13];
    float* out = (float*)d_out;

    float *h0d, *c0d, *h1d, *c1d, *hist;
    cudaGetSymbolAddress((void**)&h0d, g_h0d);
    cudaGetSymbolAddress((void**)&c0d, g_c0d);
    cudaGetSymbolAddress((void**)&h1d, g_h1d);
    cudaGetSymbolAddress((void**)&c1d, g_c1d);
    cudaGetSymbolAddress((void**)&hist, g_hist);

    cudaFuncSetAttribute(encoder_kernel,
                         cudaFuncAttributeMaxDynamicSharedMemorySize, ENC_SMEM_BYTES);

    norm_kernel<<<BATCH, 256>>>(targets);
    zero_enc_kernel<<<(BATCH * HH + 255) / 256, 256>>>();

    encoder_kernel<<<ENC_BLOCKS, 256, ENC_SMEM_BYTES>>>(
        w_ih0, w_hh0, b_ih0, b_hh0, w_ih1, w_hh1, b_ih1, b_hh1);

    replicate_kernel<<<NDEC, 256>>>();

    for (int p = 0; p < PSTEPS; p++) {
        int pa = p & 1, pb = pa ^ 1;
        dec_cell_tf32<<<dim3(NDEC / DBM, 8), 256>>>(
            hist + p + 6, w_ih0,
            nullptr, nullptr,
            h0d + pa * (NDEC * HH), w_hh0, b_ih0, b_hh0,
            c0d, h0d + pb * (NDEC * HH), c0d);
        dec_cell_tf32<<<dim3(NDEC / DBM, 8), 256>>>(
            nullptr, nullptr,
            h0d + pb * (NDEC * HH), w_ih1,
            h1d + pa * (NDEC * HH), w_hh1, b_ih1, b_hh1,
            c1d, h1d + pb * (NDEC * HH), c1d);
        head_kernel<<<(NDEC * 32 + 255) / 256, 256>>>(
            h1d + pb * (NDEC * HH), w_mu, b_mu, w_sigma, b_sigma,
            eps + (long long)p * NDEC, p);
    }

    reduce_kernel<<<(BATCH * PSTEPS * 32 + 255) / 256, 256>>>(out);
}

// round 5
// speedup vs baseline: 1.3428x; 1.0742x over previous
#include <cuda_runtime.h>
#include <math.h>

#define HH      256
#define G4      1024
#define BATCH   256
#define WIN     512
#define TT      519     // W + MAXLAG
#define MAXLAG  7
#define SREP    100
#define NDEC    25600   // BATCH * SREP
#define PSTEPS  24
#define ESTEPS  512
#define ENC_BLOCKS 128

// ---- encoder v3 smem layout (floats) ----
#define WSTR    260
#define OFF_W0  0
#define OFF_WI1 (64 * WSTR)
#define OFF_WH1 (2 * 64 * WSTR)
#define CHSZ    (32 * 20)
#define OFF_CH  (3 * 64 * WSTR)            // [2 grp][2 buf][32][20]
#define REDW    68
#define OFF_RED (OFF_CH + 4 * CHSZ)        // [32][REDW]
#define OFF_SXW (OFF_RED + 32 * REDW)      // [64][8]
#define OFF_SXA (OFF_SXW + 64 * 8)         // [32][8]
#define ENC_SMEM_FLOATS (OFF_SXA + 32 * 8)
#define ENC_SMEM_BYTES  (ENC_SMEM_FLOATS * 4)

// ---------------- scratch ----------------
__device__ __align__(128) float g_scaled[BATCH * TT];
__device__ float g_loc[BATCH];
__device__ float g_scale[BATCH];

__device__ __align__(128) float g_h0e[2][BATCH * HH];
__device__ __align__(128) float g_c0e[BATCH * HH];
__device__ __align__(128) float g_h1e[2][BATCH * HH];
__device__ __align__(128) float g_c1e[BATCH * HH];

__device__ __align__(128) float g_h0d[2][NDEC * HH];
__device__ __align__(128) float g_c0d[NDEC * HH];
__device__ __align__(128) float g_h1d[2][NDEC * HH];
__device__ __align__(128) float g_c1d[NDEC * HH];

__device__ __align__(128) float g_hist[NDEC * 32];

__device__ unsigned g_ectr = 0;     // monotonic encoder barrier counter

__device__ __forceinline__ float sigf(float x) { return 1.0f / (1.0f + expf(-x)); }

__device__ __forceinline__ float tf32_rna(float x) {
    float r;
    asm("cvt.rna.tf32.f32 %0, %1;\n" : "=f"(r) : "f"(x));
    return r;
}

#define MMA_TF32(c, a, b) \
    asm volatile("mma.sync.aligned.m16n8k8.row.col.f32.tf32.tf32.f32 " \
                 "{%0,%1,%2,%3}, {%4,%5,%6,%7}, {%8,%9}, {%0,%1,%2,%3};\n" \
                 : "+f"((c)[0]), "+f"((c)[1]), "+f"((c)[2]), "+f"((c)[3]) \
                 : "r"((a)[0]), "r"((a)[1]), "r"((a)[2]), "r"((a)[3]), \
                   "r"((b)[0]), "r"((b)[1]))

// ---------------- normalization ----------------
__global__ void norm_kernel(const float* __restrict__ tp) {
    int b = blockIdx.x;
    int tid = threadIdx.x;
    const float* row = tp + b * TT;

    double s = 0.0, q = 0.0;
    for (int j = tid; j < WIN; j += blockDim.x) {
        double v = (double)row[MAXLAG + j];
        s += v; q += v * v;
    }
    __shared__ double ss[256], sq[256];
    ss[tid] = s; sq[tid] = q;
    __syncthreads();
    for (int o = 128; o > 0; o >>= 1) {
        if (tid < o) { ss[tid] += ss[tid + o]; sq[tid] += sq[tid + o]; }
        __syncthreads();
    }
    __shared__ float smean, sscale;
    if (tid == 0) {
        double mean = ss[0] / (double)WIN;
        double var  = sq[0] / (double)WIN - mean * mean;
        if (var < 0.0) var = 0.0;
        float sd = (float)sqrt(var);
        float sc = (sd < 1e-10f) ? 1.0f : sd;
        smean = (float)mean; sscale = sc;
        g_loc[b] = (float)mean; g_scale[b] = sc;
    }
    __syncthreads();
    float m = smean, sc = sscale;
    for (int j = tid; j < TT; j += blockDim.x)
        g_scaled[b * TT + j] = (row[j] - m) / sc;
}

__global__ void zero_enc_kernel() {
    int i = blockIdx.x * blockDim.x + threadIdx.x;
    if (i < BATCH * HH) {
        g_h0e[0][i] = 0.f; g_c0e[i] = 0.f;
        g_h1e[0][i] = 0.f; g_c1e[i] = 0.f;
    }
    if (i == 0) g_ectr = 0;
}

// ---------------- persistent encoder v3: tf32 mma, 512 threads, split-K ----------------
// 128 blocks; block = 32 batch x 16 units (64 gate rows). 16 warps in 2 K-groups
// of 8; each group tiles 32x64 as (2 m16) x (4 n16), K halved per group.
// Weights fp32 in smem for the whole kernel; 3-pass tf32 split for accuracy.
__global__ void __launch_bounds__(512) encoder_kernel(
    const float* __restrict__ w_ih0, const float* __restrict__ w_hh0,
    const float* __restrict__ b_ih0, const float* __restrict__ b_hh0,
    const float* __restrict__ w_ih1, const float* __restrict__ w_hh1,
    const float* __restrict__ b_ih1, const float* __restrict__ b_hh1)
{
    extern __shared__ float es[];
    float* W0  = es + OFF_W0;
    float* WI1 = es + OFF_WI1;
    float* WH1 = es + OFF_WH1;
    float* RED = es + OFF_RED;
    float* SXW = es + OFF_SXW;
    float* SXA = es + OFF_SXA;

    const int t    = threadIdx.x;
    const int lane = t & 31;
    const int w    = t >> 5;
    const int grp  = w >> 3;            // K-group 0/1
    const int wl   = w & 7;
    const int m_w  = (wl & 1) * 16;
    const int n_w  = (wl >> 1) * 16;
    const int qr   = lane >> 2;
    const int qc   = lane & 3;
    const int b0   = (blockIdx.x & 7) * 32;
    const int u0   = (blockIdx.x >> 3) * 16;

    // ---- load weight slices into smem once ----
    for (int i = t; i < 64 * 64; i += 512) {
        int r  = i >> 6;
        int c4 = i & 63;
        int grow = u0 + (r & 15) + ((r >> 4) << 8);
        *(float4*)(W0  + r * WSTR + c4 * 4) = *(const float4*)(w_hh0 + grow * 256 + c4 * 4);
        *(float4*)(WI1 + r * WSTR + c4 * 4) = *(const float4*)(w_ih1 + grow * 256 + c4 * 4);
        *(float4*)(WH1 + r * WSTR + c4 * 4) = *(const float4*)(w_hh1 + grow * 256 + c4 * 4);
    }
    if (t < 64) {
        int grow = u0 + (t & 15) + ((t >> 4) << 8);
#pragma unroll
        for (int k = 0; k < 7; k++) SXW[t * 8 + k] = w_ih0[grow * 7 + k];
    }

    // epilogue-thread constants (t < 256): unit = u0 + (t&15), rows t>>4 and +16
    const int eul = t & 15;
    const int er  = t >> 4;
    float bI0 = 0, bF0 = 0, bG0 = 0, bO0 = 0, bI1 = 0, bF1 = 0, bG1 = 0, bO1 = 0;
    if (t < 256) {
        int u = u0 + eul;
        bI0 = b_ih0[u]       + b_hh0[u];
        bF0 = b_ih0[u + 256] + b_hh0[u + 256];
        bG0 = b_ih0[u + 512] + b_hh0[u + 512];
        bO0 = b_ih0[u + 768] + b_hh0[u + 768];
        bI1 = b_ih1[u]       + b_hh1[u];
        bF1 = b_ih1[u + 256] + b_hh1[u + 256];
        bG1 = b_ih1[u + 512] + b_hh1[u + 512];
        bO1 = b_ih1[u + 768] + b_hh1[u + 768];
    }
    __syncthreads();

    const int gt   = t & 255;
    const int prow = gt >> 3;
    const int pcol = (gt & 7) * 2;
    float* CH = es + OFF_CH + grp * (2 * CHSZ);

    // tf32 3-pass GEMM over this group's K half (nchunks k16-chunks)
    auto gemm_tc = [&](const float* act, const float* wsm, int nchunks, float (&acc)[2][4]) {
        const int kb = grp * (nchunks * 16);
        {
            float2 p = __ldcg((const float2*)(act + (b0 + prow) * HH + kb + pcol));
            CH[prow * 20 + pcol]     = p.x;
            CH[prow * 20 + pcol + 1] = p.y;
        }
        __syncthreads();
        for (int ch = 0; ch < nchunks; ch++) {
            float2 nxt;
            const bool have = (ch + 1) < nchunks;
            if (have)
                nxt = __ldcg((const float2*)(act + (b0 + prow) * HH + kb + (ch + 1) * 16 + pcol));
            const float* hb = CH + (ch & 1) * CHSZ;
            const int kcol = kb + ch * 16;
#pragma unroll
            for (int ks = 0; ks < 2; ks++) {
                const int kk = ks * 8;
                float a0 = hb[(m_w + qr) * 20 + kk + qc];
                float a1 = hb[(m_w + qr + 8) * 20 + kk + qc];
                float a2 = hb[(m_w + qr) * 20 + kk + qc + 4];
                float a3 = hb[(m_w + qr + 8) * 20 + kk + qc + 4];
                float h0_ = tf32_rna(a0), h1_ = tf32_rna(a1), h2_ = tf32_rna(a2), h3_ = tf32_rna(a3);
                unsigned ahi[4] = {__float_as_uint(h0_), __float_as_uint(h1_),
                                   __float_as_uint(h2_), __float_as_uint(h3_)};
                unsigned alo[4] = {__float_as_uint(tf32_rna(a0 - h0_)),
                                   __float_as_uint(tf32_rna(a1 - h1_)),
                                   __float_as_uint(tf32_rna(a2 - h2_)),
                                   __float_as_uint(tf32_rna(a3 - h3_))};
#pragma unroll
                for (int f = 0; f < 2; f++) {
                    const float* wr = wsm + (n_w + f * 8 + qr) * WSTR + kcol + kk;
                    float v0 = wr[qc], v1 = wr[qc + 4];
                    float w0_ = tf32_rna(v0), w1_ = tf32_rna(v1);
                    unsigned bhi[2] = {__float_as_uint(w0_), __float_as_uint(w1_)};
                    unsigned blo[2] = {__float_as_uint(tf32_rna(v0 - w0_)),
                                       __float_as_uint(tf32_rna(v1 - w1_))};
                    MMA_TF32(acc[f], ahi, bhi);
                    MMA_TF32(acc[f], ahi, blo);
                    MMA_TF32(acc[f], alo, bhi);
                }
            }
            if (have) {
                float* d = CH + ((ch + 1) & 1) * CHSZ + prow * 20 + pcol;
                d[0] = nxt.x; d[1] = nxt.y;
            }
            __syncthreads();
        }
    };

    // split-K combine: group1 stores partials, group0 adds its own in place
    auto reduce_store = [&](float (&acc)[2][4]) {
        if (grp == 1) {
#pragma unroll
            for (int f = 0; f < 2; f++)
#pragma unroll
                for (int half = 0; half < 2; half++)
#pragma unroll
                    for (int j = 0; j < 2; j++)
                        RED[(m_w + qr + half * 8) * REDW + n_w + f * 8 + 2 * qc + j] =
                            acc[f][half * 2 + j];
        }
        __syncthreads();
        if (grp == 0) {
#pragma unroll
            for (int f = 0; f < 2; f++)
#pragma unroll
                for (int half = 0; half < 2; half++)
#pragma unroll
                    for (int j = 0; j < 2; j++)
                        RED[(m_w + qr + half * 8) * REDW + n_w + f * 8 + 2 * qc + j] +=
                            acc[f][half * 2 + j];
        }
        __syncthreads();
    };

    for (int step = 0; step < ESTEPS; step++) {
        const int pa = step & 1, pb = pa ^ 1;
        float* h0b = g_h0e[pb];
        float* h1b = g_h1e[pb];

        // lag inputs for this step
        if (t < 32) {
            const float* xr = g_scaled + (b0 + t) * TT + step + 6;
#pragma unroll
            for (int k = 0; k < 7; k++) SXA[t * 8 + k] = xr[-k];
        }

        // ===== phase A : layer 0 =====
        float acc[2][4];
#pragma unroll
        for (int f = 0; f < 2; f++)
#pragma unroll
            for (int r = 0; r < 4; r++) acc[f][r] = 0.f;

        gemm_tc(g_h0e[pa], W0, 8, acc);
        reduce_store(acc);

        if (t < 256) {
#pragma unroll
            for (int h2 = 0; h2 < 2; h2++) {
                int r = er + 16 * h2;
                float gi = RED[r * REDW + eul]      + bI0;
                float gf = RED[r * REDW + 16 + eul] + bF0;
                float gg = RED[r * REDW + 32 + eul] + bG0;
                float go = RED[r * REDW + 48 + eul] + bO0;
#pragma unroll
                for (int k = 0; k < 7; k++) {
                    float x = SXA[r * 8 + k];
                    gi = fmaf(x, SXW[eul * 8 + k], gi);
                    gf = fmaf(x, SXW[(16 + eul) * 8 + k], gf);
                    gg = fmaf(x, SXW[(32 + eul) * 8 + k], gg);
                    go = fmaf(x, SXW[(48 + eul) * 8 + k], go);
                }
                int idx = (b0 + r) * HH + (u0 + eul);
                float c = g_c0e[idx];
                float cn = sigf(gf) * c + sigf(gi) * tanhf(gg);
                g_c0e[idx] = cn;
                h0b[idx] = sigf(go) * tanhf(cn);
            }
        }
        __syncthreads();
        if (t == 0) { __threadfence(); atomicAdd(&g_ectr, 1u); }

        // ===== phase B : layer 1 =====
#pragma unroll
        for (int f = 0; f < 2; f++)
#pragma unroll
            for (int r = 0; r < 4; r++) acc[f][r] = 0.f;

        // w_hh1 GEMM first — needs only h1 from step-1 (cheap wait)
        if (t == 0) {
            unsigned tgt = 256u * (unsigned)step;
            while (*(volatile unsigned*)&g_ectr < tgt) { }
        }
        __syncthreads();
        gemm_tc(g_h1e[pa], WH1, 8, acc);

        // w_ih1 GEMM — needs h0_new from ALL unit-tiles (the real wait)
        if (t == 0) {
            unsigned tgt = 256u * (unsigned)step + 128u;
            while (*(volatile unsigned*)&g_ectr < tgt) { }
        }
        __syncthreads();
        gemm_tc(h0b, WI1, 8, acc);

        reduce_store(acc);

        if (t < 256) {
#pragma unroll
            for (int h2 = 0; h2 < 2; h2++) {
                int r = er + 16 * h2;
                float gi = RED[r * REDW + eul]      + bI1;
                float gf = RED[r * REDW + 16 + eul] + bF1;
                float gg = RED[r * REDW + 32 + eul] + bG1;
                float go = RED[r * REDW + 48 + eul] + bO1;
                int idx = (b0 + r) * HH + (u0 + eul);
                float c = g_c1e[idx];
                float cn = sigf(gf) * c + sigf(gi) * tanhf(gg);
                g_c1e[idx] = cn;
                h1b[idx] = sigf(go) * tanhf(cn);
            }
        }
        __syncthreads();
        if (t == 0) { __threadfence(); atomicAdd(&g_ectr, 1u); }
    }
}

// ---------------- decoder cell: tf32 tensor-core GEMM + fused LSTM (passed R3/R4) ----------------
#define DBM 128
#define DBK 16
#define DPAD 20

__global__ void __launch_bounds__(256) dec_cell_tf32(
    const float* __restrict__ xs,
    const float* __restrict__ w_ihs,
    const float* __restrict__ xb,
    const float* __restrict__ w_ihb,
    const float* __restrict__ h_in,
    const float* __restrict__ w_hh,
    const float* __restrict__ b_ih, const float* __restrict__ b_hh,
    const float* __restrict__ c_in,
    float* __restrict__ h_out, float* __restrict__ c_out)
{
    __shared__ float sAhi[DBM][DPAD];
    __shared__ float sAlo[DBM][DPAD];
    __shared__ float sBhi[DBM][DPAD];
    __shared__ float sBlo[DBM][DPAD];
    __shared__ float sBias[128];

    const int t    = threadIdx.x;
    const int lane = t & 31;
    const int wid  = t >> 5;
    const int m0w  = (wid & 1) * 64;
    const int u0w  = (wid >> 1) * 8;
    const int b0   = blockIdx.x * DBM;
    const int u0   = blockIdx.y * 32;

    const int lrow = t >> 1;
    const int lc0  = (t & 1) * 8;
    const int lgrow = u0 + (lrow & 31) + ((lrow >> 5) << 8);

    if (t < 128) {
        int grow = u0 + (t & 31) + ((t >> 5) << 8);
        sBias[t] = b_ih[grow] + b_hh[grow];
    }

    float acc[4][4][4];
#pragma unroll
    for (int mi = 0; mi < 4; mi++)
#pragma unroll
        for (int g = 0; g < 4; g++)
#pragma unroll
            for (int r = 0; r < 4; r++) acc[mi][g][r] = 0.f;

    const int qr = lane >> 2;
    const int qc = lane & 3;

    auto compute_chunk = [&]() {
#pragma unroll
        for (int ks = 0; ks < 2; ks++) {
            const int kk = ks * 8;
            unsigned ahi[4][4], alo[4][4];
#pragma unroll
            for (int mi = 0; mi < 4; mi++) {
                int r  = m0w + mi * 16 + qr;
                int c  = kk + qc;
                ahi[mi][0] = __float_as_uint(sAhi[r][c]);
                ahi[mi][1] = __float_as_uint(sAhi[r + 8][c]);
                ahi[mi][2] = __float_as_uint(sAhi[r][c + 4]);
                ahi[mi][3] = __float_as_uint(sAhi[r + 8][c + 4]);
                alo[mi][0] = __float_as_uint(sAlo[r][c]);
                alo[mi][1] = __float_as_uint(sAlo[r + 8][c]);
                alo[mi][2] = __float_as_uint(sAlo[r][c + 4]);
                alo[mi][3] = __float_as_uint(sAlo[r + 8][c + 4]);
            }
            unsigned bhi[4][2], blo[4][2];
#pragma unroll
            for (int g = 0; g < 4; g++) {
                int br = g * 32 + u0w + qr;
                int c  = kk + qc;
                bhi[g][0] = __float_as_uint(sBhi[br][c]);
                bhi[g][1] = __float_as_uint(sBhi[br][c + 4]);
                blo[g][0] = __float_as_uint(sBlo[br][c]);
                blo[g][1] = __float_as_uint(sBlo[br][c + 4]);
            }
#pragma unroll
            for (int mi = 0; mi < 4; mi++)
#pragma unroll
                for (int g = 0; g < 4; g++) {
                    MMA_TF32(acc[mi][g], ahi[mi], bhi[g]);
                    MMA_TF32(acc[mi][g], ahi[mi], blo[g]);
                    MMA_TF32(acc[mi][g], alo[mi], bhi[g]);
                }
        }
    };

    auto split_store_a = [&](int col, float v) {
        float h_ = tf32_rna(v);
        sAhi[lrow][col] = h_;
        sAlo[lrow][col] = tf32_rna(v - h_);
    };
    auto split_store_b = [&](int col, float v) {
        float h_ = tf32_rna(v);
        sBhi[lrow][col] = h_;
        sBlo[lrow][col] = tf32_rna(v - h_);
    };

    if (xs != nullptr) {
        __syncthreads();
#pragma unroll
        for (int cc = 0; cc < 8; cc++) {
            int k = lc0 + cc;
            float va = (k < 7) ? xs[(b0 + lrow) * 32 - k] : 0.f;
            float vb = (k < 7) ? w_ihs[lgrow * 7 + k] : 0.f;
            split_store_a(k, va);
            split_store_b(k, vb);
        }
        __syncthreads();
        compute_chunk();
    }

    auto gemm_segment = [&](const float* __restrict__ act, const float* __restrict__ wgt) {
        for (int k0 = 0; k0 < HH; k0 += DBK) {
            __syncthreads();
            const float* ar = act + (long long)(b0 + lrow) * HH + k0 + lc0;
            float4 a0 = *(const float4*)(ar);
            float4 a1 = *(const float4*)(ar + 4);
            const float* wr = wgt + (long long)lgrow * HH + k0 + lc0;
            float4 w0 = *(const float4*)(wr);
            float4 w1 = *(const float4*)(wr + 4);
            split_store_a(lc0 + 0, a0.x); split_store_a(lc0 + 1, a0.y);
            split_store_a(lc0 + 2, a0.z); split_store_a(lc0 + 3, a0.w);
            split_store_a(lc0 + 4, a1.x); split_store_a(lc0 + 5, a1.y);
            split_store_a(lc0 + 6, a1.z); split_store_a(lc0 + 7, a1.w);
            split_store_b(lc0 + 0, w0.x); split_store_b(lc0 + 1, w0.y);
            split_store_b(lc0 + 2, w0.z); split_store_b(lc0 + 3, w0.w);
            split_store_b(lc0 + 4, w1.x); split_store_b(lc0 + 5, w1.y);
            split_store_b(lc0 + 6, w1.z); split_store_b(lc0 + 7, w1.w);
            __syncthreads();
            compute_chunk();
        }
    };

    if (xb != nullptr) gemm_segment(xb, w_ihb);
    gemm_segment(h_in, w_hh);

#pragma unroll
    for (int mi = 0; mi < 4; mi++) {
        int rbase = b0 + m0w + mi * 16 + qr;
#pragma unroll
        for (int half = 0; half < 2; half++) {
            int row = rbase + half * 8;
#pragma unroll
            for (int j = 0; j < 2; j++) {
                int ucol = 2 * qc + j;
                int u = u0 + u0w + ucol;
                int ci = half * 2 + j;
                float gi_ = acc[mi][0][ci] + sBias[ 0 + u0w + ucol];
                float gf  = acc[mi][1][ci] + sBias[32 + u0w + ucol];
                float gg  = acc[mi][2][ci] + sBias[64 + u0w + ucol];
                float go  = acc[mi][3][ci] + sBias[96 + u0w + ucol];
                long long idx = (long long)row * HH + u;
                float c = c_in[idx];
                float cn = sigf(gf) * c + sigf(gi_) * tanhf(gg);
                float hn = sigf(go) * tanhf(cn);
                c_out[idx] = cn;
                h_out[idx] = hn;
            }
        }
    }
}

// ---------------- replicate encoder state x100 + init history ----------------
__global__ void replicate_kernel() {
    int row = blockIdx.x;
    int u   = threadIdx.x;
    int b   = row / SREP;
    long long d = (long long)row * HH + u;
    long long s = (long long)b * HH + u;
    g_h0d[0][d] = g_h0e[0][s];
    g_c0d[d]    = g_c0e[s];
    g_h1d[0][d] = g_h1e[0][s];
    g_c1d[d]    = g_c1e[s];
    if (u < MAXLAG) g_hist[row * 32 + u] = g_scaled[b * TT + WIN + u];
}

// ---------------- mu/sigma head + sampling ----------------
__global__ void head_kernel(const float* __restrict__ h1,
                            const float* __restrict__ w_mu, const float* __restrict__ b_mu,
                            const float* __restrict__ w_sig, const float* __restrict__ b_sig,
                            const float* __restrict__ eps_p, int p) {
    int gid  = blockIdx.x * blockDim.x + threadIdx.x;
    int warp = gid >> 5;
    int lane = gid & 31;
    if (warp >= NDEC) return;
    const float* hr = h1 + (long long)warp * HH;
    float mu = 0.f, sg = 0.f;
#pragma unroll
    for (int k = lane; k < HH; k += 32) {
        float h = hr[k];
        mu = fmaf(h, w_mu[k], mu);
        sg = fmaf(h, w_sig[k], sg);
    }
#pragma unroll
    for (int o = 16; o > 0; o >>= 1) {
        mu += __shfl_xor_sync(0xffffffffu, mu, o);
        sg += __shfl_xor_sync(0xffffffffu, sg, o);
    }
    if (lane == 0) {
        mu += b_mu[0];
        sg += b_sig[0];
        float sp = (sg > 20.f) ? sg : log1pf(expf(sg));
        float sample = mu + sp * eps_p[warp];
        g_hist[warp * 32 + MAXLAG + p] = sample;
    }
}

// ---------------- mean over samples + denormalize ----------------
__global__ void reduce_kernel(float* __restrict__ out) {
    int gid  = blockIdx.x * blockDim.x + threadIdx.x;
    int warp = gid >> 5;
    int lane = gid & 31;
    if (warp >= BATCH * PSTEPS) return;
    int b = warp / PSTEPS;
    int p = warp % PSTEPS;
    float s = 0.f;
    for (int ss = lane; ss < SREP; ss += 32)
        s += g_hist[(b * SREP + ss) * 32 + MAXLAG + p];
#pragma unroll
    for (int o = 16; o > 0; o >>= 1) s += __shfl_xor_sync(0xffffffffu, s, o);
    if (lane == 0)
        out[b * PSTEPS + p] = s * (1.0f / (float)SREP) * g_scale[b] + g_loc[b];
}

// ---------------- launch ----------------
extern "C" void kernel_launch(void* const* d_in, const int* in_sizes, int n_in,
                              void* d_out, int out_size) {
    const float* targets = (const float*)d_in[0];
    const float* w_ih0   = (const float*)d_in[1];
    const float* w_hh0   = (const float*)d_in[2];
    const float* b_ih0   = (const float*)d_in[3];
    const float* b_hh0   = (const float*)d_in[4];
    const float* w_ih1   = (const float*)d_in[5];
    const float* w_hh1   = (const float*)d_in[6];
    const float* b_ih1   = (const float*)d_in[7];
    const float* b_hh1   = (const float*)d_in[8];
    const float* w_mu    = (const float*)d_in[9];
    const float* b_mu    = (const float*)d_in[10];
    const float* w_sigma = (const float*)d_in[11];
    const float* b_sigma = (const float*)d_in[12];
    const float* eps     = (const float*)d_in[13];
    float* out = (float*)d_out;

    float *h0d, *c0d, *h1d, *c1d, *hist;
    cudaGetSymbolAddress((void**)&h0d, g_h0d);
    cudaGetSymbolAddress((void**)&c0d, g_c0d);
    cudaGetSymbolAddress((void**)&h1d, g_h1d);
    cudaGetSymbolAddress((void**)&c1d, g_c1d);
    cudaGetSymbolAddress((void**)&hist, g_hist);

    cudaFuncSetAttribute(encoder_kernel,
                         cudaFuncAttributeMaxDynamicSharedMemorySize, ENC_SMEM_BYTES);

    norm_kernel<<<BATCH, 256>>>(targets);
    zero_enc_kernel<<<(BATCH * HH + 255) / 256, 256>>>();

    encoder_kernel<<<ENC_BLOCKS, 512, ENC_SMEM_BYTES>>>(
        w_ih0, w_hh0, b_ih0, b_hh0, w_ih1, w_hh1, b_ih1, b_hh1);

    replicate_kernel<<<NDEC, 256>>>();

    for (int p = 0; p < PSTEPS; p++) {
        int pa = p & 1, pb = pa ^ 1;
        dec_cell_tf32<<<dim3(NDEC / DBM, 8), 256>>>(
            hist + p + 6, w_ih0,
            nullptr, nullptr,
            h0d + pa * (NDEC * HH), w_hh0, b_ih0, b_hh0,
            c0d, h0d + pb * (NDEC * HH), c0d);
        dec_cell_tf32<<<dim3(NDEC / DBM, 8), 256>>>(
            nullptr, nullptr,
            h0d + pb * (NDEC * HH), w_ih1,
            h1d + pa * (NDEC * HH), w_hh1, b_ih1, b_hh1,
            c1d, h1d + pb * (NDEC * HH), c1d);
        head_kernel<<<(NDEC * 32 + 255) / 256, 256>>>(
            h1d + pb * (NDEC * HH), w_mu, b_mu, w_sigma, b_sigma,
            eps + (long long)p * NDEC, p);
    }

    reduce_kernel<<<(BATCH * PSTEPS * 32 + 255) / 256, 256>>>(out);
}

// round 6
// speedup vs baseline: 2.1454x; 1.5977x over previous
#include <cuda_runtime.h>
#include <cuda_bf16.h>
#include <math.h>

#define HH      256
#define G4      1024
#define BATCH   256
#define WIN     512
#define TT      519     // W + MAXLAG
#define MAXLAG  7
#define SREP    100
#define NDEC    25600   // BATCH * SREP
#define PSTEPS  24
#define ESTEPS  512
#define ENC_BLOCKS 128

// ---- encoder v3 smem layout (floats) ----
#define WSTR    260
#define OFF_W0  0
#define OFF_WI1 (64 * WSTR)
#define OFF_WH1 (2 * 64 * WSTR)
#define CHSZ    (32 * 20)
#define OFF_CH  (3 * 64 * WSTR)            // [2 grp][2 buf][32][20]
#define REDW    68
#define OFF_RED (OFF_CH + 4 * CHSZ)        // [32][REDW]
#define OFF_SXW (OFF_RED + 32 * REDW)      // [64][8]
#define OFF_SXA (OFF_SXW + 64 * 8)         // [32][8]
#define ENC_SMEM_FLOATS (OFF_SXA + 32 * 8)
#define ENC_SMEM_BYTES  (ENC_SMEM_FLOATS * 4)

// ---------------- scratch ----------------
__device__ __align__(128) float g_scaled[BATCH * TT];
__device__ float g_loc[BATCH];
__device__ float g_scale[BATCH];

__device__ __align__(128) float g_h0e[2][BATCH * HH];
__device__ __align__(128) float g_c0e[BATCH * HH];
__device__ __align__(128) float g_h1e[2][BATCH * HH];
__device__ __align__(128) float g_c1e[BATCH * HH];

__device__ __align__(128) float g_h0d[2][NDEC * HH];
__device__ __align__(128) float g_c0d[NDEC * HH];
__device__ __align__(128) float g_h1d[2][NDEC * HH];
__device__ __align__(128) float g_c1d[NDEC * HH];

__device__ __align__(128) float g_hist[NDEC * 32];

__device__ unsigned g_ectr = 0;     // monotonic encoder barrier counter

__device__ __forceinline__ float sigf(float x) { return 1.0f / (1.0f + expf(-x)); }

__device__ __forceinline__ float tf32_rna(float x) {
    float r;
    asm("cvt.rna.tf32.f32 %0, %1;\n" : "=f"(r) : "f"(x));
    return r;
}

#define MMA_TF32(c, a, b) \
    asm volatile("mma.sync.aligned.m16n8k8.row.col.f32.tf32.tf32.f32 " \
                 "{%0,%1,%2,%3}, {%4,%5,%6,%7}, {%8,%9}, {%0,%1,%2,%3};\n" \
                 : "+f"((c)[0]), "+f"((c)[1]), "+f"((c)[2]), "+f"((c)[3]) \
                 : "r"((a)[0]), "r"((a)[1]), "r"((a)[2]), "r"((a)[3]), \
                   "r"((b)[0]), "r"((b)[1]))

#define MMA_BF16(c, a, b) \
    asm volatile("mma.sync.aligned.m16n8k16.row.col.f32.bf16.bf16.f32 " \
                 "{%0,%1,%2,%3}, {%4,%5,%6,%7}, {%8,%9}, {%0,%1,%2,%3};\n" \
                 : "+f"((c)[0]), "+f"((c)[1]), "+f"((c)[2]), "+f"((c)[3]) \
                 : "r"((a)[0]), "r"((a)[1]), "r"((a)[2]), "r"((a)[3]), \
                   "r"((b)[0]), "r"((b)[1]))

// split (x,y) into packed bf16x2 hi and lo; order consistent between hi/lo.
__device__ __forceinline__ void bsplit2(float x, float y, unsigned& hi, unsigned& lo) {
    __nv_bfloat16 hx = __float2bfloat16(x);
    __nv_bfloat16 hy = __float2bfloat16(y);
    __nv_bfloat162 hp = __halves2bfloat162(hx, hy);
    __nv_bfloat162 lp = __halves2bfloat162(
        __float2bfloat16(x - __bfloat162float(hx)),
        __float2bfloat16(y - __bfloat162float(hy)));
    hi = *reinterpret_cast<unsigned*>(&hp);
    lo = *reinterpret_cast<unsigned*>(&lp);
}

// ---------------- normalization ----------------
__global__ void norm_kernel(const float* __restrict__ tp) {
    int b = blockIdx.x;
    int tid = threadIdx.x;
    const float* row = tp + b * TT;

    double s = 0.0, q = 0.0;
    for (int j = tid; j < WIN; j += blockDim.x) {
        double v = (double)row[MAXLAG + j];
        s += v; q += v * v;
    }
    __shared__ double ss[256], sq[256];
    ss[tid] = s; sq[tid] = q;
    __syncthreads();
    for (int o = 128; o > 0; o >>= 1) {
        if (tid < o) { ss[tid] += ss[tid + o]; sq[tid] += sq[tid + o]; }
        __syncthreads();
    }
    __shared__ float smean, sscale;
    if (tid == 0) {
        double mean = ss[0] / (double)WIN;
        double var  = sq[0] / (double)WIN - mean * mean;
        if (var < 0.0) var = 0.0;
        float sd = (float)sqrt(var);
        float sc = (sd < 1e-10f) ? 1.0f : sd;
        smean = (float)mean; sscale = sc;
        g_loc[b] = (float)mean; g_scale[b] = sc;
    }
    __syncthreads();
    float m = smean, sc = sscale;
    for (int j = tid; j < TT; j += blockDim.x)
        g_scaled[b * TT + j] = (row[j] - m) / sc;
}

__global__ void zero_enc_kernel() {
    int i = blockIdx.x * blockDim.x + threadIdx.x;
    if (i < BATCH * HH) {
        g_h0e[0][i] = 0.f; g_c0e[i] = 0.f;
        g_h1e[0][i] = 0.f; g_c1e[i] = 0.f;
    }
    if (i == 0) g_ectr = 0;
}

// ---------------- persistent encoder v3 (unchanged, passed R5) ----------------
__global__ void __launch_bounds__(512) encoder_kernel(
    const float* __restrict__ w_ih0, const float* __restrict__ w_hh0,
    const float* __restrict__ b_ih0, const float* __restrict__ b_hh0,
    const float* __restrict__ w_ih1, const float* __restrict__ w_hh1,
    const float* __restrict__ b_ih1, const float* __restrict__ b_hh1)
{
    extern __shared__ float es[];
    float* W0  = es + OFF_W0;
    float* WI1 = es + OFF_WI1;
    float* WH1 = es + OFF_WH1;
    float* RED = es + OFF_RED;
    float* SXW = es + OFF_SXW;
    float* SXA = es + OFF_SXA;

    const int t    = threadIdx.x;
    const int lane = t & 31;
    const int w    = t >> 5;
    const int grp  = w >> 3;
    const int wl   = w & 7;
    const int m_w  = (wl & 1) * 16;
    const int n_w  = (wl >> 1) * 16;
    const int qr   = lane >> 2;
    const int qc   = lane & 3;
    const int b0   = (blockIdx.x & 7) * 32;
    const int u0   = (blockIdx.x >> 3) * 16;

    for (int i = t; i < 64 * 64; i += 512) {
        int r  = i >> 6;
        int c4 = i & 63;
        int grow = u0 + (r & 15) + ((r >> 4) << 8);
        *(float4*)(W0  + r * WSTR + c4 * 4) = *(const float4*)(w_hh0 + grow * 256 + c4 * 4);
        *(float4*)(WI1 + r * WSTR + c4 * 4) = *(const float4*)(w_ih1 + grow * 256 + c4 * 4);
        *(float4*)(WH1 + r * WSTR + c4 * 4) = *(const float4*)(w_hh1 + grow * 256 + c4 * 4);
    }
    if (t < 64) {
        int grow = u0 + (t & 15) + ((t >> 4) << 8);
#pragma unroll
        for (int k = 0; k < 7; k++) SXW[t * 8 + k] = w_ih0[grow * 7 + k];
    }

    const int eul = t & 15;
    const int er  = t >> 4;
    float bI0 = 0, bF0 = 0, bG0 = 0, bO0 = 0, bI1 = 0, bF1 = 0, bG1 = 0, bO1 = 0;
    if (t < 256) {
        int u = u0 + eul;
        bI0 = b_ih0[u]       + b_hh0[u];
        bF0 = b_ih0[u + 256] + b_hh0[u + 256];
        bG0 = b_ih0[u + 512] + b_hh0[u + 512];
        bO0 = b_ih0[u + 768] + b_hh0[u + 768];
        bI1 = b_ih1[u]       + b_hh1[u];
        bF1 = b_ih1[u + 256] + b_hh1[u + 256];
        bG1 = b_ih1[u + 512] + b_hh1[u + 512];
        bO1 = b_ih1[u + 768] + b_hh1[u + 768];
    }
    __syncthreads();

    const int gt   = t & 255;
    const int prow = gt >> 3;
    const int pcol = (gt & 7) * 2;
    float* CH = es + OFF_CH + grp * (2 * CHSZ);

    auto gemm_tc = [&](const float* act, const float* wsm, int nchunks, float (&acc)[2][4]) {
        const int kb = grp * (nchunks * 16);
        {
            float2 p = __ldcg((const float2*)(act + (b0 + prow) * HH + kb + pcol));
            CH[prow * 20 + pcol]     = p.x;
            CH[prow * 20 + pcol + 1] = p.y;
        }
        __syncthreads();
        for (int ch = 0; ch < nchunks; ch++) {
            float2 nxt;
            const bool have = (ch + 1) < nchunks;
            if (have)
                nxt = __ldcg((const float2*)(act + (b0 + prow) * HH + kb + (ch + 1) * 16 + pcol));
            const float* hb = CH + (ch & 1) * CHSZ;
            const int kcol = kb + ch * 16;
#pragma unroll
            for (int ks = 0; ks < 2; ks++) {
                const int kk = ks * 8;
                float a0 = hb[(m_w + qr) * 20 + kk + qc];
                float a1 = hb[(m_w + qr + 8) * 20 + kk + qc];
                float a2 = hb[(m_w + qr) * 20 + kk + qc + 4];
                float a3 = hb[(m_w + qr + 8) * 20 + kk + qc + 4];
                float h0_ = tf32_rna(a0), h1_ = tf32_rna(a1), h2_ = tf32_rna(a2), h3_ = tf32_rna(a3);
                unsigned ahi[4] = {__float_as_uint(h0_), __float_as_uint(h1_),
                                   __float_as_uint(h2_), __float_as_uint(h3_)};
                unsigned alo[4] = {__float_as_uint(tf32_rna(a0 - h0_)),
                                   __float_as_uint(tf32_rna(a1 - h1_)),
                                   __float_as_uint(tf32_rna(a2 - h2_)),
                                   __float_as_uint(tf32_rna(a3 - h3_))};
#pragma unroll
                for (int f = 0; f < 2; f++) {
                    const float* wr = wsm + (n_w + f * 8 + qr) * WSTR + kcol + kk;
                    float v0 = wr[qc], v1 = wr[qc + 4];
                    float w0_ = tf32_rna(v0), w1_ = tf32_rna(v1);
                    unsigned bhi[2] = {__float_as_uint(w0_), __float_as_uint(w1_)};
                    unsigned blo[2] = {__float_as_uint(tf32_rna(v0 - w0_)),
                                       __float_as_uint(tf32_rna(v1 - w1_))};
                    MMA_TF32(acc[f], ahi, bhi);
                    MMA_TF32(acc[f], ahi, blo);
                    MMA_TF32(acc[f], alo, bhi);
                }
            }
            if (have) {
                float* d = CH + ((ch + 1) & 1) * CHSZ + prow * 20 + pcol;
                d[0] = nxt.x; d[1] = nxt.y;
            }
            __syncthreads();
        }
    };

    auto reduce_store = [&](float (&acc)[2][4]) {
        if (grp == 1) {
#pragma unroll
            for (int f = 0; f < 2; f++)
#pragma unroll
                for (int half = 0; half < 2; half++)
#pragma unroll
                    for (int j = 0; j < 2; j++)
                        RED[(m_w + qr + half * 8) * REDW + n_w + f * 8 + 2 * qc + j] =
                            acc[f][half * 2 + j];
        }
        __syncthreads();
        if (grp == 0) {
#pragma unroll
            for (int f = 0; f < 2; f++)
#pragma unroll
                for (int half = 0; half < 2; half++)
#pragma unroll
                    for (int j = 0; j < 2; j++)
                        RED[(m_w + qr + half * 8) * REDW + n_w + f * 8 + 2 * qc + j] +=
                            acc[f][half * 2 + j];
        }
        __syncthreads();
    };

    for (int step = 0; step < ESTEPS; step++) {
        const int pa = step & 1, pb = pa ^ 1;
        float* h0b = g_h0e[pb];
        float* h1b = g_h1e[pb];

        if (t < 32) {
            const float* xr = g_scaled + (b0 + t) * TT + step + 6;
#pragma unroll
            for (int k = 0; k < 7; k++) SXA[t * 8 + k] = xr[-k];
        }

        float acc[2][4];
#pragma unroll
        for (int f = 0; f < 2; f++)
#pragma unroll
            for (int r = 0; r < 4; r++) acc[f][r] = 0.f;

        gemm_tc(g_h0e[pa], W0, 8, acc);
        reduce_store(acc);

        if (t < 256) {
#pragma unroll
            for (int h2 = 0; h2 < 2; h2++) {
                int r = er + 16 * h2;
                float gi = RED[r * REDW + eul]      + bI0;
                float gf = RED[r * REDW + 16 + eul] + bF0;
                float gg = RED[r * REDW + 32 + eul] + bG0;
                float go = RED[r * REDW + 48 + eul] + bO0;
#pragma unroll
                for (int k = 0; k < 7; k++) {
                    float x = SXA[r * 8 + k];
                    gi = fmaf(x, SXW[eul * 8 + k], gi);
                    gf = fmaf(x, SXW[(16 + eul) * 8 + k], gf);
                    gg = fmaf(x, SXW[(32 + eul) * 8 + k], gg);
                    go = fmaf(x, SXW[(48 + eul) * 8 + k], go);
                }
                int idx = (b0 + r) * HH + (u0 + eul);
                float c = g_c0e[idx];
                float cn = sigf(gf) * c + sigf(gi) * tanhf(gg);
                g_c0e[idx] = cn;
                h0b[idx] = sigf(go) * tanhf(cn);
            }
        }
        __syncthreads();
        if (t == 0) { __threadfence(); atomicAdd(&g_ectr, 1u); }

#pragma unroll
        for (int f = 0; f < 2; f++)
#pragma unroll
            for (int r = 0; r < 4; r++) acc[f][r] = 0.f;

        if (t == 0) {
            unsigned tgt = 256u * (unsigned)step;
            while (*(volatile unsigned*)&g_ectr < tgt) { }
        }
        __syncthreads();
        gemm_tc(g_h1e[pa], WH1, 8, acc);

        if (t == 0) {
            unsigned tgt = 256u * (unsigned)step + 128u;
            while (*(volatile unsigned*)&g_ectr < tgt) { }
        }
        __syncthreads();
        gemm_tc(h0b, WI1, 8, acc);

        reduce_store(acc);

        if (t < 256) {
#pragma unroll
            for (int h2 = 0; h2 < 2; h2++) {
                int r = er + 16 * h2;
                float gi = RED[r * REDW + eul]      + bI1;
                float gf = RED[r * REDW + 16 + eul] + bF1;
                float gg = RED[r * REDW + 32 + eul] + bG1;
                float go = RED[r * REDW + 48 + eul] + bO1;
                int idx = (b0 + r) * HH + (u0 + eul);
                float c = g_c1e[idx];
                float cn = sigf(gf) * c + sigf(gi) * tanhf(gg);
                g_c1e[idx] = cn;
                h1b[idx] = sigf(go) * tanhf(cn);
            }
        }
        __syncthreads();
        if (t == 0) { __threadfence(); atomicAdd(&g_ectr, 1u); }
    }
}

// ---------------- decoder cell: bf16 m16n8k16 3-pass split + fused LSTM ----------------
// Block: 128 batch x 32 units (128 gate cols). 8 warps; warp = (wid&1)*64 rows,
// (wid>>1)*8 units. Packed bf16x2 smem, row stride 12 uints (conflict-free).
#define DBM 128
#define DPK 12

__global__ void __launch_bounds__(256) dec_cell_bf16(
    const float* __restrict__ xs,        // lag base (g_hist + p + 6) or null
    const float* __restrict__ w_ihs,     // (1024,7)
    const float* __restrict__ xb,        // big x (N,256) or null
    const float* __restrict__ w_ihb,     // (1024,256)
    const float* __restrict__ h_in,      // (N,256)
    const float* __restrict__ w_hh,      // (1024,256)
    const float* __restrict__ b_ih, const float* __restrict__ b_hh,
    const float* __restrict__ c_in,
    float* __restrict__ h_out, float* __restrict__ c_out)
{
    __shared__ unsigned sAhi[DBM][DPK];
    __shared__ unsigned sAlo[DBM][DPK];
    __shared__ unsigned sBhi[DBM][DPK];
    __shared__ unsigned sBlo[DBM][DPK];
    __shared__ float sBias[128];

    const int t    = threadIdx.x;
    const int lane = t & 31;
    const int wid  = t >> 5;
    const int m0w  = (wid & 1) * 64;
    const int u0w  = (wid >> 1) * 8;
    const int b0   = blockIdx.x * DBM;
    const int u0   = blockIdx.y * 32;

    const int lrow = t >> 1;             // 0..127
    const int lc0  = (t & 1) * 8;        // float col base (0 or 8)
    const int lp0  = (t & 1) * 4;        // packed col base (0 or 4)
    const int lgrow = u0 + (lrow & 31) + ((lrow >> 5) << 8);

    if (t < 128) {
        int grow = u0 + (t & 31) + ((t >> 5) << 8);
        sBias[t] = b_ih[grow] + b_hh[grow];
    }

    float acc[4][4][4];
#pragma unroll
    for (int mi = 0; mi < 4; mi++)
#pragma unroll
        for (int g = 0; g < 4; g++)
#pragma unroll
            for (int r = 0; r < 4; r++) acc[mi][g][r] = 0.f;

    const int qr = lane >> 2;
    const int qc = lane & 3;

    // one bf16 k16 chunk: 16 A-frag loads (hi+lo), 16 B-frag loads, 48 MMA
    auto compute_chunk = [&]() {
        unsigned ahi[4][4], alo[4][4];
#pragma unroll
        for (int mi = 0; mi < 4; mi++) {
            int r = m0w + mi * 16 + qr;
            ahi[mi][0] = sAhi[r][qc];     ahi[mi][1] = sAhi[r + 8][qc];
            ahi[mi][2] = sAhi[r][qc + 4]; ahi[mi][3] = sAhi[r + 8][qc + 4];
            alo[mi][0] = sAlo[r][qc];     alo[mi][1] = sAlo[r + 8][qc];
            alo[mi][2] = sAlo[r][qc + 4]; alo[mi][3] = sAlo[r + 8][qc + 4];
        }
        unsigned bhi[4][2], blo[4][2];
#pragma unroll
        for (int g = 0; g < 4; g++) {
            int br = g * 32 + u0w + qr;
            bhi[g][0] = sBhi[br][qc]; bhi[g][1] = sBhi[br][qc + 4];
            blo[g][0] = sBlo[br][qc]; blo[g][1] = sBlo[br][qc + 4];
        }
#pragma unroll
        for (int mi = 0; mi < 4; mi++)
#pragma unroll
            for (int g = 0; g < 4; g++) {
                MMA_BF16(acc[mi][g], ahi[mi], bhi[g]);
                MMA_BF16(acc[mi][g], ahi[mi], blo[g]);
                MMA_BF16(acc[mi][g], alo[mi], bhi[g]);
            }
    };

    // store 8 floats (4 packed pairs) into A or B tiles
    auto store_a8 = [&](const float* v) {
        unsigned hi[4], lo[4];
#pragma unroll
        for (int j = 0; j < 4; j++) bsplit2(v[2 * j], v[2 * j + 1], hi[j], lo[j]);
        *(uint4*)&sAhi[lrow][lp0] = make_uint4(hi[0], hi[1], hi[2], hi[3]);
        *(uint4*)&sAlo[lrow][lp0] = make_uint4(lo[0], lo[1], lo[2], lo[3]);
    };
    auto store_b8 = [&](const float* v) {
        unsigned hi[4], lo[4];
#pragma unroll
        for (int j = 0; j < 4; j++) bsplit2(v[2 * j], v[2 * j + 1], hi[j], lo[j]);
        *(uint4*)&sBhi[lrow][lp0] = make_uint4(hi[0], hi[1], hi[2], hi[3]);
        *(uint4*)&sBlo[lrow][lp0] = make_uint4(lo[0], lo[1], lo[2], lo[3]);
    };

    // -------- lag chunk (K=7 zero-padded to 16) --------
    if (xs != nullptr) {
        float va[8], vb[8];
#pragma unroll
        for (int cc = 0; cc < 8; cc++) {
            int k = lc0 + cc;
            va[cc] = (k < 7) ? xs[(b0 + lrow) * 32 - k] : 0.f;
            vb[cc] = (k < 7) ? w_ihs[lgrow * 7 + k] : 0.f;
        }
        store_a8(va);
        store_b8(vb);
        __syncthreads();
        compute_chunk();
    }

    // -------- dense K=256 segments --------
    auto gemm_segment = [&](const float* __restrict__ act, const float* __restrict__ wgt) {
        for (int k0 = 0; k0 < HH; k0 += 16) {
            __syncthreads();
            float av[8], wv[8];
            *(float4*)(av)     = *(const float4*)(act + (long long)(b0 + lrow) * HH + k0 + lc0);
            *(float4*)(av + 4) = *(const float4*)(act + (long long)(b0 + lrow) * HH + k0 + lc0 + 4);
            *(float4*)(wv)     = *(const float4*)(wgt + (long long)lgrow * HH + k0 + lc0);
            *(float4*)(wv + 4) = *(const float4*)(wgt + (long long)lgrow * HH + k0 + lc0 + 4);
            store_a8(av);
            store_b8(wv);
            __syncthreads();
            compute_chunk();
        }
    };

    if (xb != nullptr) gemm_segment(xb, w_ihb);
    gemm_segment(h_in, w_hh);

    // -------- epilogue: fused LSTM nonlinearity --------
#pragma unroll
    for (int mi = 0; mi < 4; mi++) {
        int rbase = b0 + m0w + mi * 16 + qr;
#pragma unroll
        for (int half = 0; half < 2; half++) {
            int row = rbase + half * 8;
#pragma unroll
            for (int j = 0; j < 2; j++) {
                int ucol = 2 * qc + j;
                int u = u0 + u0w + ucol;
                int ci = half * 2 + j;
                float gi_ = acc[mi][0][ci] + sBias[ 0 + u0w + ucol];
                float gf  = acc[mi][1][ci] + sBias[32 + u0w + ucol];
                float gg  = acc[mi][2][ci] + sBias[64 + u0w + ucol];
                float go  = acc[mi][3][ci] + sBias[96 + u0w + ucol];
                long long idx = (long long)row * HH + u;
                float c = c_in[idx];
                float cn = sigf(gf) * c + sigf(gi_) * tanhf(gg);
                float hn = sigf(go) * tanhf(cn);
                c_out[idx] = cn;
                h_out[idx] = hn;
            }
        }
    }
}

// ---------------- replicate encoder state x100 + init history ----------------
__global__ void replicate_kernel() {
    int row = blockIdx.x;
    int u   = threadIdx.x;
    int b   = row / SREP;
    long long d = (long long)row * HH + u;
    long long s = (long long)b * HH + u;
    g_h0d[0][d] = g_h0e[0][s];
    g_c0d[d]    = g_c0e[s];
    g_h1d[0][d] = g_h1e[0][s];
    g_c1d[d]    = g_c1e[s];
    if (u < MAXLAG) g_hist[row * 32 + u] = g_scaled[b * TT + WIN + u];
}

// ---------------- mu/sigma head + sampling ----------------
__global__ void head_kernel(const float* __restrict__ h1,
                            const float* __restrict__ w_mu, const float* __restrict__ b_mu,
                            const float* __restrict__ w_sig, const float* __restrict__ b_sig,
                            const float* __restrict__ eps_p, int p) {
    int gid  = blockIdx.x * blockDim.x + threadIdx.x;
    int warp = gid >> 5;
    int lane = gid & 31;
    if (warp >= NDEC) return;
    const float* hr = h1 + (long long)warp * HH;
    float mu = 0.f, sg = 0.f;
#pragma unroll
    for (int k = lane; k < HH; k += 32) {
        float h = hr[k];
        mu = fmaf(h, w_mu[k], mu);
        sg = fmaf(h, w_sig[k], sg);
    }
#pragma unroll
    for (int o = 16; o > 0; o >>= 1) {
        mu += __shfl_xor_sync(0xffffffffu, mu, o);
        sg += __shfl_xor_sync(0xffffffffu, sg, o);
    }
    if (lane == 0) {
        mu += b_mu[0];
        sg += b_sig[0];
        float sp = (sg > 20.f) ? sg : log1pf(expf(sg));
        float sample = mu + sp * eps_p[warp];
        g_hist[warp * 32 + MAXLAG + p] = sample;
    }
}

// ---------------- mean over samples + denormalize ----------------
__global__ void reduce_kernel(float* __restrict__ out) {
    int gid  = blockIdx.x * blockDim.x + threadIdx.x;
    int warp = gid >> 5;
    int lane = gid & 31;
    if (warp >= BATCH * PSTEPS) return;
    int b = warp / PSTEPS;
    int p = warp % PSTEPS;
    float s = 0.f;
    for (int ss = lane; ss < SREP; ss += 32)
        s += g_hist[(b * SREP + ss) * 32 + MAXLAG + p];
#pragma unroll
    for (int o = 16; o > 0; o >>= 1) s += __shfl_xor_sync(0xffffffffu, s, o);
    if (lane == 0)
        out[b * PSTEPS + p] = s * (1.0f / (float)SREP) * g_scale[b] + g_loc[b];
}

// ---------------- launch ----------------
extern "C" void kernel_launch(void* const* d_in, const int* in_sizes, int n_in,
                              void* d_out, int out_size) {
    const float* targets = (const float*)d_in[0];
    const float* w_ih0   = (const float*)d_in[1];
    const float* w_hh0   = (const float*)d_in[2];
    const float* b_ih0   = (const float*)d_in[3];
    const float* b_hh0   = (const float*)d_in[4];
    const float* w_ih1   = (const float*)d_in[5];
    const float* w_hh1   = (const float*)d_in[6];
    const float* b_ih1   = (const float*)d_in[7];
    const float* b_hh1   = (const float*)d_in[8];
    const float* w_mu    = (const float*)d_in[9];
    const float* b_mu    = (const float*)d_in[10];
    const float* w_sigma = (const float*)d_in[11];
    const float* b_sigma = (const float*)d_in[12];
    const float* eps     = (const float*)d_in[13];
    float* out = (float*)d_out;

    float *h0d, *c0d, *h1d, *c1d, *hist;
    cudaGetSymbolAddress((void**)&h0d, g_h0d);
    cudaGetSymbolAddress((void**)&c0d, g_c0d);
    cudaGetSymbolAddress((void**)&h1d, g_h1d);
    cudaGetSymbolAddress((void**)&c1d, g_c1d);
    cudaGetSymbolAddress((void**)&hist, g_hist);

    cudaFuncSetAttribute(encoder_kernel,
                         cudaFuncAttributeMaxDynamicSharedMemorySize, ENC_SMEM_BYTES);

    norm_kernel<<<BATCH, 256>>>(targets);
    zero_enc_kernel<<<(BATCH * HH + 255) / 256, 256>>>();

    encoder_kernel<<<ENC_BLOCKS, 512, ENC_SMEM_BYTES>>>(
        w_ih0, w_hh0, b_ih0, b_hh0, w_ih1, w_hh1, b_ih1, b_hh1);

    replicate_kernel<<<NDEC, 256>>>();

    for (int p = 0; p < PSTEPS; p++) {
        int pa = p & 1, pb = pa ^ 1;
        dec_cell_bf16<<<dim3(NDEC / DBM, 8), 256>>>(
            hist + p + 6, w_ih0,
            nullptr, nullptr,
            h0d + pa * (NDEC * HH), w_hh0, b_ih0, b_hh0,
            c0d, h0d + pb * (NDEC * HH), c0d);
        dec_cell_bf16<<<dim3(NDEC / DBM, 8), 256>>>(
            nullptr, nullptr,
            h0d + pb * (NDEC * HH), w_ih1,
            h1d + pa * (NDEC * HH), w_hh1, b_ih1, b_hh1,
            c1d, h1d + pb * (NDEC * HH), c1d);
        head_kernel<<<(NDEC * 32 + 255) / 256, 256>>>(
            h1d + pb * (NDEC * HH), w_mu, b_mu, w_sigma, b_sigma,
            eps + (long long)p * NDEC, p);
    }

    reduce_kernel<<<(BATCH * PSTEPS * 32 + 255) / 256, 256>>>(out);
}